// round 2
// baseline (speedup 1.0000x reference)
#include <cuda_runtime.h>
#include <math.h>

#define BB    4
#define TPP   4
#define TFF   2
#define NPAIR (BB*TFF)      // 8
#define RAD   4
#define NS    81            // (2*RAD+1)^2
#define NFR   (BB*TPP)      // 16

// ---------------- scratch (static device globals; no allocations) ----------------
__device__ int   g_idx[NPAIR];
__device__ int   g_needed[NFR];
__device__ float g_pf0[(size_t)NFR * 128 * 6400];   // 52.4 MB
__device__ float g_pf1[(size_t)NFR * 256 * 1600];   // 26.2 MB
__device__ float g_pf2[(size_t)NFR * 512 * 400];    // 13.1 MB

// ---------------- prep: replicate _interp_indices + needed-frame flags -----------
__global__ void prep_kernel(const int* __restrict__ pci, const int* __restrict__ fci)
{
    if (threadIdx.x != 0 || blockIdx.x != 0) return;
    for (int n = 0; n < NFR; n++) g_needed[n] = 0;
    for (int i = 0; i < BB; i++) {
        int p_pos = TPP - 2;
        for (int j = 0; j < TFF; j++) {
            int f_i = fci[i * TFF + j];
            while (p_pos >= 0) {
                if (p_pos == 0 || f_i < -pci[i * TPP + p_pos - 1]) {
                    int id = p_pos + i * TPP;
                    g_idx[i * TFF + j] = id;
                    g_needed[id] = 1;
                    break;
                }
                p_pos--;
            }
        }
        g_needed[i * TPP + (TPP - 1)] = 1;   // f1 frame
    }
}

// ---------------- conv (1x1) + BN + SiLU :  GEMM  out[d,p] = sum_c w[d,c] x[c,p] --
// 128x128 tile, 256 threads, 8x8 per thread, K-chunk = 16.
__global__ void __launch_bounds__(256) conv_kernel(
    const float* __restrict__ x,  const float* __restrict__ wgt,
    const float* __restrict__ gg, const float* __restrict__ bbp,
    const float* __restrict__ mm, const float* __restrict__ vv,
    float* __restrict__ pf, int C, int HW)
{
    int n = blockIdx.z;
    if (!g_needed[n]) return;

    const int p0  = blockIdx.x * 128;
    const int d0  = blockIdx.y * 128;
    const int tid = threadIdx.x;
    const int tx  = tid & 15;
    const int ty  = tid >> 4;

    __shared__ float Wt[16][132];   // Wt[c][d]
    __shared__ float Xt[16][132];   // Xt[c][p]

    float acc[8][8];
#pragma unroll
    for (int i = 0; i < 8; i++)
#pragma unroll
        for (int j = 0; j < 8; j++) acc[i][j] = 0.f;

    const float* xn = x + (size_t)n * C * HW;

    for (int k0 = 0; k0 < C; k0 += 16) {
        // W tile: 128 d-rows x 16 c-cols, stored transposed
#pragma unroll
        for (int it = 0; it < 2; it++) {
            int f  = tid + it * 256;          // 0..511 float4 slots
            int dr = f >> 2;
            int c4 = (f & 3) * 4;
            float4 wv = *(const float4*)(wgt + (size_t)(d0 + dr) * C + k0 + c4);
            Wt[c4 + 0][dr] = wv.x; Wt[c4 + 1][dr] = wv.y;
            Wt[c4 + 2][dr] = wv.z; Wt[c4 + 3][dr] = wv.w;
        }
        // X tile: 16 c-rows x 128 pixels
#pragma unroll
        for (int it = 0; it < 2; it++) {
            int f   = tid + it * 256;
            int row = f >> 5;
            int col = (f & 31) * 4;
            float4 xv = make_float4(0.f, 0.f, 0.f, 0.f);
            if (p0 + col < HW)
                xv = *(const float4*)(xn + (size_t)(k0 + row) * HW + p0 + col);
            *(float4*)&Xt[row][col] = xv;
        }
        __syncthreads();
#pragma unroll
        for (int kk = 0; kk < 16; kk++) {
            float4 a0 = *(const float4*)&Wt[kk][ty * 8];
            float4 a1 = *(const float4*)&Wt[kk][ty * 8 + 4];
            float4 b0 = *(const float4*)&Xt[kk][tx * 8];
            float4 b1 = *(const float4*)&Xt[kk][tx * 8 + 4];
            float a[8] = {a0.x, a0.y, a0.z, a0.w, a1.x, a1.y, a1.z, a1.w};
            float b[8] = {b0.x, b0.y, b0.z, b0.w, b1.x, b1.y, b1.z, b1.w};
#pragma unroll
            for (int i = 0; i < 8; i++)
#pragma unroll
                for (int j = 0; j < 8; j++)
                    acc[i][j] = fmaf(a[i], b[j], acc[i][j]);
        }
        __syncthreads();
    }

    // epilogue: BN affine + SiLU
#pragma unroll
    for (int i = 0; i < 8; i++) {
        int d = d0 + ty * 8 + i;
        float sc = gg[d] * (1.0f / sqrtf(vv[d] + 1e-5f));
        float bi = bbp[d] - mm[d] * sc;
        float* op = pf + ((size_t)n * C + d) * HW;
#pragma unroll
        for (int j = 0; j < 8; j++) {
            int p = p0 + tx * 8 + j;
            if (p < HW) {
                float y = acc[i][j] * sc + bi;
                float s = 1.0f / (1.0f + expf(-y));
                op[p] = y * s;
            }
        }
    }
}

// ---------------- correlation + softmax + mlp dot --------------------------------
// one block per (channel c, pair n). f1 zero-padded in smem, f2 in registers.
template<int C, int H, int W, int STEP, int FP2>
__global__ void __launch_bounds__(256) corr_kernel(
    const float* __restrict__ pf, const float* __restrict__ mlpw,
    float* __restrict__ out, int out_off)
{
    constexpr int PAD = RAD * STEP;
    constexpr int W2  = W + 2 * PAD;
    constexpr int H2  = H + 2 * PAD;
    constexpr int HW  = H * W;

    extern __shared__ float sm[];
    float* f1p  = sm;                 // H2*W2 padded f1 plane
    float* wred = sm + H2 * W2;       // [8 warps][81] partials

    const int c   = blockIdx.x;
    const int n   = blockIdx.y;
    const int b   = n / TFF;
    const int n1  = b * TPP + (TPP - 1);
    const int n2  = g_idx[n];
    const int tid = threadIdx.x;
    const int wid = tid >> 5;
    const int lane = tid & 31;

    const float* f1g = pf + ((size_t)n1 * C + c) * HW;
    const float* f2g = pf + ((size_t)n2 * C + c) * HW;

    // fill padded f1 (single pass, zeros in the halo)
    for (int q = tid; q < H2 * W2; q += 256) {
        int hh = q / W2 - PAD;
        int ww = q % W2 - PAD;
        float v = 0.f;
        if ((unsigned)hh < (unsigned)H && (unsigned)ww < (unsigned)W)
            v = f1g[hh * W + ww];
        f1p[q] = v;
    }

    // f2 pixels of this thread -> registers; precompute padded base address
    float f2r[FP2];
    int   basek[FP2];
#pragma unroll
    for (int k = 0; k < FP2; k++) {
        int p = tid + k * 256;
        if (p < HW) {
            f2r[k]   = f2g[p];
            basek[k] = (p / W + PAD) * W2 + (p % W) + PAD;
        } else {
            f2r[k]   = 0.f;
            basek[k] = PAD * W2 + PAD;   // safe interior address, contributes 0
        }
    }
    __syncthreads();

    // 81 offsets: per-offset dot over this thread's pixels, warp-reduce, store
    for (int oy = 0; oy < 9; oy++) {
        int dy = (oy - RAD) * STEP;
#pragma unroll
        for (int ox = 0; ox < 9; ox++) {
            int dx   = (ox - RAD) * STEP;
            int soff = dy * W2 + dx;
            float aa[4] = {0.f, 0.f, 0.f, 0.f};
#pragma unroll
            for (int k = 0; k < FP2; k++)
                aa[k & 3] = fmaf(f1p[basek[k] + soff], f2r[k], aa[k & 3]);
            float v = (aa[0] + aa[1]) + (aa[2] + aa[3]);
#pragma unroll
            for (int o = 16; o; o >>= 1)
                v += __shfl_xor_sync(0xffffffffu, v, o);
            if (lane == 0) wred[wid * NS + oy * 9 + ox] = v;
        }
    }
    __syncthreads();

    // softmax over 81 + dot with mlp_w (one warp; deterministic fixed-order sums)
    if (tid < 32) {
        float v0 = -1e30f, v1 = -1e30f, v2 = -1e30f;
        {
            float s0 = 0.f, s1 = 0.f, s2 = 0.f;
#pragma unroll
            for (int w = 0; w < 8; w++) {
                s0 += wred[w * NS + tid];
                if (tid + 32 < NS) s1 += wred[w * NS + tid + 32];
                if (tid + 64 < NS) s2 += wred[w * NS + tid + 64];
            }
            v0 = s0;
            if (tid + 32 < NS) v1 = s1;
            if (tid + 64 < NS) v2 = s2;
        }
        float mx = fmaxf(v0, fmaxf(v1, v2));
#pragma unroll
        for (int o = 16; o; o >>= 1)
            mx = fmaxf(mx, __shfl_xor_sync(0xffffffffu, mx, o));
        float e0 = expf(v0 - mx);
        float e1 = (tid + 32 < NS) ? expf(v1 - mx) : 0.f;
        float e2 = (tid + 64 < NS) ? expf(v2 - mx) : 0.f;
        float w0 = mlpw[tid];
        float w1 = (tid + 32 < NS) ? mlpw[tid + 32] : 0.f;
        float w2 = (tid + 64 < NS) ? mlpw[tid + 64] : 0.f;
        float ssum = e0 + e1 + e2;
        float dot  = e0 * w0 + e1 * w1 + e2 * w2;
#pragma unroll
        for (int o = 16; o; o >>= 1) {
            ssum += __shfl_xor_sync(0xffffffffu, ssum, o);
            dot  += __shfl_xor_sync(0xffffffffu, dot,  o);
        }
        if (tid == 0)
            out[out_off + n * C + c] = dot / ssum;
    }
}

// ---------------- launch ---------------------------------------------------------
extern "C" void kernel_launch(void* const* d_in, const int* in_sizes, int n_in,
                              void* d_out, int out_size)
{
    // Two possible metadata orderings:
    //  (a) reference-signature order: f0,f1,f2, w0,g0,b0,m0,v0, w1,..., w2,..., mlp,pci,fci
    //  (b) setup_inputs dict order:   f0,w0,g0,b0,m0,v0, f1,w1,g1,b1,m1,v1, f2,..., mlp,pci,fci
    // Disambiguate via in_sizes[1]: (a) -> 4*4*256*40*40 = 6553600 ; (b) -> 128*128 = 16384.
    // mapped slots: 0:f0 1:f1 2:f2 3..7:w0,g0,b0,m0,v0 8..12:lvl1 13..17:lvl2 18:mlp 19:pci 20:fci
    int map_sig [21] = {0,1,2, 3,4,5,6,7, 8,9,10,11,12, 13,14,15,16,17, 18,19,20};
    int map_dict[21] = {0,6,12, 1,2,3,4,5, 7,8,9,10,11, 13,14,15,16,17, 18,19,20};
    const int* map = (in_sizes[1] == 16384) ? map_dict : map_sig;

    const float* f0 = (const float*)d_in[map[0]];
    const float* f1 = (const float*)d_in[map[1]];
    const float* f2 = (const float*)d_in[map[2]];
    const float* w0 = (const float*)d_in[map[3]];
    const float* g0 = (const float*)d_in[map[4]];
    const float* b0 = (const float*)d_in[map[5]];
    const float* m0 = (const float*)d_in[map[6]];
    const float* v0 = (const float*)d_in[map[7]];
    const float* w1 = (const float*)d_in[map[8]];
    const float* g1 = (const float*)d_in[map[9]];
    const float* b1 = (const float*)d_in[map[10]];
    const float* m1 = (const float*)d_in[map[11]];
    const float* v1 = (const float*)d_in[map[12]];
    const float* w2 = (const float*)d_in[map[13]];
    const float* g2 = (const float*)d_in[map[14]];
    const float* b2 = (const float*)d_in[map[15]];
    const float* m2 = (const float*)d_in[map[16]];
    const float* v2 = (const float*)d_in[map[17]];
    const float* mlpw = (const float*)d_in[map[18]];
    const int*   pci  = (const int*)d_in[map[19]];
    const int*   fci  = (const int*)d_in[map[20]];
    float* out = (float*)d_out;

    void *p0v, *p1v, *p2v;
    cudaGetSymbolAddress(&p0v, g_pf0);
    cudaGetSymbolAddress(&p1v, g_pf1);
    cudaGetSymbolAddress(&p2v, g_pf2);
    float* pf0 = (float*)p0v;
    float* pf1 = (float*)p1v;
    float* pf2 = (float*)p2v;

    prep_kernel<<<1, 1>>>(pci, fci);

    conv_kernel<<<dim3(50, 1, NFR), 256>>>(f0, w0, g0, b0, m0, v0, pf0, 128, 6400);
    conv_kernel<<<dim3(13, 2, NFR), 256>>>(f1, w1, g1, b1, m1, v1, pf1, 256, 1600);
    conv_kernel<<<dim3( 4, 4, NFR), 256>>>(f2, w2, g2, b2, m2, v2, pf2, 512,  400);

    // level 0 corr needs >48KB dynamic smem (padded 112x112 plane)
    size_t sm0 = (size_t)(112 * 112 + 8 * NS) * sizeof(float);   // ~52.8 KB
    size_t sm1 = (size_t)( 56 *  56 + 8 * NS) * sizeof(float);
    size_t sm2 = (size_t)( 28 *  28 + 8 * NS) * sizeof(float);
    cudaFuncSetAttribute(corr_kernel<128, 80, 80, 4, 25>,
                         cudaFuncAttributeMaxDynamicSharedMemorySize, 65536);

    corr_kernel<128, 80, 80, 4, 25><<<dim3(128, NPAIR), 256, sm0>>>(pf0, mlpw, out, 0);
    corr_kernel<256, 40, 40, 2,  7><<<dim3(256, NPAIR), 256, sm1>>>(pf1, mlpw, out, 1024);
    corr_kernel<512, 20, 20, 1,  2><<<dim3(512, NPAIR), 256, sm2>>>(pf2, mlpw, out, 3072);
}

// round 3
// speedup vs baseline: 1.1204x; 1.1204x over previous
#include <cuda_runtime.h>
#include <math.h>
#include <stdint.h>

#define BB    4
#define TPP   4
#define TFF   2
#define NPAIR (BB*TFF)      // 8
#define RAD   4
#define NS    81
#define NFR   (BB*TPP)      // 16

// ---------------- scratch (static device globals; no allocations) ----------------
__device__ int   g_idx[NPAIR];
__device__ int   g_needed[NFR];
__device__ float g_pf0[(size_t)NFR * 128 * 6400];
__device__ float g_pf1[(size_t)NFR * 256 * 1600];
__device__ float g_pf2[(size_t)NFR * 512 * 400];

// ---------------- prep ------------------------------------------------------------
__global__ void prep_kernel(const int* __restrict__ pci, const int* __restrict__ fci)
{
    if (threadIdx.x != 0 || blockIdx.x != 0) return;
    for (int n = 0; n < NFR; n++) g_needed[n] = 0;
    for (int i = 0; i < BB; i++) {
        int p_pos = TPP - 2;
        for (int j = 0; j < TFF; j++) {
            int f_i = fci[i * TFF + j];
            while (p_pos >= 0) {
                if (p_pos == 0 || f_i < -pci[i * TPP + p_pos - 1]) {
                    int id = p_pos + i * TPP;
                    g_idx[i * TFF + j] = id;
                    g_needed[id] = 1;
                    break;
                }
                p_pos--;
            }
        }
        g_needed[i * TPP + (TPP - 1)] = 1;
    }
}

// ---------------- tf32 helpers ----------------------------------------------------
__device__ __forceinline__ uint32_t f2tf(float v)
{
    uint32_t r;
    asm("cvt.rna.tf32.f32 %0, %1;" : "=r"(r) : "f"(v));
    return r;
}

__device__ __forceinline__ void mma8(float* c, const uint32_t* a, const uint32_t* b)
{
    asm volatile(
        "mma.sync.aligned.m16n8k8.row.col.f32.tf32.tf32.f32 "
        "{%0,%1,%2,%3}, {%4,%5,%6,%7}, {%8,%9}, {%0,%1,%2,%3};"
        : "+f"(c[0]), "+f"(c[1]), "+f"(c[2]), "+f"(c[3])
        : "r"(a[0]), "r"(a[1]), "r"(a[2]), "r"(a[3]), "r"(b[0]), "r"(b[1]));
}

__device__ __forceinline__ float silu(float y)
{
    return y / (1.0f + expf(-y));
}

// ---------------- conv (1x1) + BN + SiLU, tf32 3-term tensor GEMM -----------------
// out[d,p] = sum_c W[d,c] X[c,p].  Block tile 128(d) x 128(p), K-chunk 16.
// 8 warps as 2(m) x 4(n): warp tile 64x32 = 4 m-atoms x 4 n-atoms of m16n8k8.
__global__ void __launch_bounds__(256) conv_tf32_kernel(
    const float* __restrict__ x,  const float* __restrict__ wgt,
    const float* __restrict__ gg, const float* __restrict__ bbp,
    const float* __restrict__ mm, const float* __restrict__ vv,
    float* __restrict__ pf, int C, int HW)
{
    int n = blockIdx.z;
    if (!g_needed[n]) return;

    const int tid  = threadIdx.x;
    const int lane = tid & 31;
    const int wid  = tid >> 5;
    const int p0   = blockIdx.x * 128;
    const int d0   = blockIdx.y * 128;
    const int m_off = (wid & 1) * 64;        // d offset within block tile
    const int n_off = (wid >> 1) * 32;       // p offset within block tile
    const int g  = lane >> 2;                // group id 0..7
    const int tg = lane & 3;                 // thread-in-group 0..3

    // A: [m=128][k=16] stride 20 (conflict-free frag reads)
    // B: [k=16][n=128] stride 136
    __shared__ uint32_t Ah[128 * 20], Al[128 * 20];
    __shared__ uint32_t Bh[16 * 136], Bl[16 * 136];

    float acc[4][4][4];
#pragma unroll
    for (int mi = 0; mi < 4; mi++)
#pragma unroll
        for (int ni = 0; ni < 4; ni++)
#pragma unroll
            for (int r = 0; r < 4; r++) acc[mi][ni][r] = 0.f;

    const float* xn = x + (size_t)n * C * HW;

    for (int k0 = 0; k0 < C; k0 += 16) {
        // --- stage A (weights) : 128 rows x 16 cols = 512 float4 slots ---
#pragma unroll
        for (int it = 0; it < 2; it++) {
            int f   = tid + it * 256;
            int row = f >> 2;
            int c4  = (f & 3) * 4;
            float4 wv = *(const float4*)(wgt + (size_t)(d0 + row) * C + k0 + c4);
            float vx[4] = {wv.x, wv.y, wv.z, wv.w};
            uint32_t h[4], l[4];
#pragma unroll
            for (int j = 0; j < 4; j++) {
                h[j] = f2tf(vx[j]);
                l[j] = f2tf(vx[j] - __uint_as_float(h[j]));
            }
            *(uint4*)&Ah[row * 20 + c4] = make_uint4(h[0], h[1], h[2], h[3]);
            *(uint4*)&Al[row * 20 + c4] = make_uint4(l[0], l[1], l[2], l[3]);
        }
        // --- stage B (features) : 16 rows x 128 cols = 512 float4 slots ---
#pragma unroll
        for (int it = 0; it < 2; it++) {
            int f   = tid + it * 256;
            int row = f >> 5;
            int c4  = (f & 31) * 4;
            float4 xv = make_float4(0.f, 0.f, 0.f, 0.f);
            if (p0 + c4 < HW)
                xv = *(const float4*)(xn + (size_t)(k0 + row) * HW + p0 + c4);
            float vx[4] = {xv.x, xv.y, xv.z, xv.w};
            uint32_t h[4], l[4];
#pragma unroll
            for (int j = 0; j < 4; j++) {
                h[j] = f2tf(vx[j]);
                l[j] = f2tf(vx[j] - __uint_as_float(h[j]));
            }
            *(uint4*)&Bh[row * 136 + c4] = make_uint4(h[0], h[1], h[2], h[3]);
            *(uint4*)&Bl[row * 136 + c4] = make_uint4(l[0], l[1], l[2], l[3]);
        }
        __syncthreads();

#pragma unroll
        for (int ka = 0; ka < 2; ka++) {
            uint32_t bh[4][2], bl[4][2];
#pragma unroll
            for (int ni = 0; ni < 4; ni++) {
                int ab = (ka * 8 + tg) * 136 + n_off + ni * 8 + g;
                bh[ni][0] = Bh[ab];            bh[ni][1] = Bh[ab + 4 * 136];
                bl[ni][0] = Bl[ab];            bl[ni][1] = Bl[ab + 4 * 136];
            }
#pragma unroll
            for (int mi = 0; mi < 4; mi++) {
                int aa = (m_off + mi * 16 + g) * 20 + ka * 8 + tg;
                uint32_t ah[4] = {Ah[aa], Ah[aa + 160], Ah[aa + 4], Ah[aa + 164]};
                uint32_t al[4] = {Al[aa], Al[aa + 160], Al[aa + 4], Al[aa + 164]};
#pragma unroll
                for (int ni = 0; ni < 4; ni++) {
                    mma8(acc[mi][ni], ah, bh[ni]);   // hi*hi
                    mma8(acc[mi][ni], ah, bl[ni]);   // hi*lo
                    mma8(acc[mi][ni], al, bh[ni]);   // lo*hi
                }
            }
        }
        __syncthreads();
    }

    // --- epilogue: BN affine + SiLU, float2 stores ---
#pragma unroll
    for (int mi = 0; mi < 4; mi++) {
        int r0 = d0 + m_off + mi * 16 + g;
        int r1 = r0 + 8;
        float sc0 = gg[r0] * (1.0f / sqrtf(vv[r0] + 1e-5f));
        float bi0 = bbp[r0] - mm[r0] * sc0;
        float sc1 = gg[r1] * (1.0f / sqrtf(vv[r1] + 1e-5f));
        float bi1 = bbp[r1] - mm[r1] * sc1;
        float* op0 = pf + ((size_t)n * C + r0) * HW;
        float* op1 = pf + ((size_t)n * C + r1) * HW;
#pragma unroll
        for (int ni = 0; ni < 4; ni++) {
            int p = p0 + n_off + ni * 8 + 2 * tg;
            if (p < HW) {
                float2 o0 = make_float2(silu(acc[mi][ni][0] * sc0 + bi0),
                                        silu(acc[mi][ni][1] * sc0 + bi0));
                float2 o1 = make_float2(silu(acc[mi][ni][2] * sc1 + bi1),
                                        silu(acc[mi][ni][3] * sc1 + bi1));
                *(float2*)(op0 + p) = o0;
                *(float2*)(op1 + p) = o1;
            }
        }
    }
}

// ---------------- correlation + softmax + mlp dot ---------------------------------
template<int C, int H, int W, int STEP, int FP2>
__global__ void __launch_bounds__(256) corr_kernel(
    const float* __restrict__ pf, const float* __restrict__ mlpw,
    float* __restrict__ out, int out_off)
{
    constexpr int PAD = RAD * STEP;
    constexpr int W2  = W + 2 * PAD;
    constexpr int H2  = H + 2 * PAD;
    constexpr int HW  = H * W;

    extern __shared__ float sm[];
    float* f1p  = sm;
    float* wred = sm + H2 * W2;

    const int c    = blockIdx.x;
    const int n    = blockIdx.y;
    const int b    = n / TFF;
    const int n1   = b * TPP + (TPP - 1);
    const int n2   = g_idx[n];
    const int tid  = threadIdx.x;
    const int wid  = tid >> 5;
    const int lane = tid & 31;

    const float* f1g = pf + ((size_t)n1 * C + c) * HW;
    const float* f2g = pf + ((size_t)n2 * C + c) * HW;

    for (int q = tid; q < H2 * W2; q += 256) {
        int hh = q / W2 - PAD;
        int ww = q % W2 - PAD;
        float v = 0.f;
        if ((unsigned)hh < (unsigned)H && (unsigned)ww < (unsigned)W)
            v = f1g[hh * W + ww];
        f1p[q] = v;
    }

    float f2r[FP2];
    int   basek[FP2];
#pragma unroll
    for (int k = 0; k < FP2; k++) {
        int p = tid + k * 256;
        if (p < HW) {
            f2r[k]   = f2g[p];
            basek[k] = (p / W + PAD) * W2 + (p % W) + PAD;
        } else {
            f2r[k]   = 0.f;
            basek[k] = PAD * W2 + PAD;
        }
    }
    __syncthreads();

    for (int oy = 0; oy < 9; oy++) {
        int dy = (oy - RAD) * STEP;
#pragma unroll
        for (int ox = 0; ox < 9; ox++) {
            int dx   = (ox - RAD) * STEP;
            int soff = dy * W2 + dx;
            float aa[4] = {0.f, 0.f, 0.f, 0.f};
#pragma unroll
            for (int k = 0; k < FP2; k++)
                aa[k & 3] = fmaf(f1p[basek[k] + soff], f2r[k], aa[k & 3]);
            float v = (aa[0] + aa[1]) + (aa[2] + aa[3]);
#pragma unroll
            for (int o = 16; o; o >>= 1)
                v += __shfl_xor_sync(0xffffffffu, v, o);
            if (lane == 0) wred[wid * NS + oy * 9 + ox] = v;
        }
    }
    __syncthreads();

    if (tid < 32) {
        float v0 = -1e30f, v1 = -1e30f, v2 = -1e30f;
        {
            float s0 = 0.f, s1 = 0.f, s2 = 0.f;
#pragma unroll
            for (int w = 0; w < 8; w++) {
                s0 += wred[w * NS + tid];
                if (tid + 32 < NS) s1 += wred[w * NS + tid + 32];
                if (tid + 64 < NS) s2 += wred[w * NS + tid + 64];
            }
            v0 = s0;
            if (tid + 32 < NS) v1 = s1;
            if (tid + 64 < NS) v2 = s2;
        }
        float mx = fmaxf(v0, fmaxf(v1, v2));
#pragma unroll
        for (int o = 16; o; o >>= 1)
            mx = fmaxf(mx, __shfl_xor_sync(0xffffffffu, mx, o));
        float e0 = expf(v0 - mx);
        float e1 = (tid + 32 < NS) ? expf(v1 - mx) : 0.f;
        float e2 = (tid + 64 < NS) ? expf(v2 - mx) : 0.f;
        float w0 = mlpw[tid];
        float w1 = (tid + 32 < NS) ? mlpw[tid + 32] : 0.f;
        float w2 = (tid + 64 < NS) ? mlpw[tid + 64] : 0.f;
        float ssum = e0 + e1 + e2;
        float dot  = e0 * w0 + e1 * w1 + e2 * w2;
#pragma unroll
        for (int o = 16; o; o >>= 1) {
            ssum += __shfl_xor_sync(0xffffffffu, ssum, o);
            dot  += __shfl_xor_sync(0xffffffffu, dot,  o);
        }
        if (tid == 0)
            out[out_off + n * C + c] = dot / ssum;
    }
}

// ---------------- launch ----------------------------------------------------------
extern "C" void kernel_launch(void* const* d_in, const int* in_sizes, int n_in,
                              void* d_out, int out_size)
{
    int map_sig [21] = {0,1,2, 3,4,5,6,7, 8,9,10,11,12, 13,14,15,16,17, 18,19,20};
    int map_dict[21] = {0,6,12, 1,2,3,4,5, 7,8,9,10,11, 13,14,15,16,17, 18,19,20};
    const int* map = (in_sizes[1] == 16384) ? map_dict : map_sig;

    const float* f0 = (const float*)d_in[map[0]];
    const float* f1 = (const float*)d_in[map[1]];
    const float* f2 = (const float*)d_in[map[2]];
    const float* w0 = (const float*)d_in[map[3]];
    const float* g0 = (const float*)d_in[map[4]];
    const float* b0 = (const float*)d_in[map[5]];
    const float* m0 = (const float*)d_in[map[6]];
    const float* v0 = (const float*)d_in[map[7]];
    const float* w1 = (const float*)d_in[map[8]];
    const float* g1 = (const float*)d_in[map[9]];
    const float* b1 = (const float*)d_in[map[10]];
    const float* m1 = (const float*)d_in[map[11]];
    const float* v1 = (const float*)d_in[map[12]];
    const float* w2 = (const float*)d_in[map[13]];
    const float* g2 = (const float*)d_in[map[14]];
    const float* b2 = (const float*)d_in[map[15]];
    const float* m2 = (const float*)d_in[map[16]];
    const float* v2 = (const float*)d_in[map[17]];
    const float* mlpw = (const float*)d_in[map[18]];
    const int*   pci  = (const int*)d_in[map[19]];
    const int*   fci  = (const int*)d_in[map[20]];
    float* out = (float*)d_out;

    void *p0v, *p1v, *p2v;
    cudaGetSymbolAddress(&p0v, g_pf0);
    cudaGetSymbolAddress(&p1v, g_pf1);
    cudaGetSymbolAddress(&p2v, g_pf2);
    float* pf0 = (float*)p0v;
    float* pf1 = (float*)p1v;
    float* pf2 = (float*)p2v;

    prep_kernel<<<1, 1>>>(pci, fci);

    conv_tf32_kernel<<<dim3(50, 1, NFR), 256>>>(f0, w0, g0, b0, m0, v0, pf0, 128, 6400);
    conv_tf32_kernel<<<dim3(13, 2, NFR), 256>>>(f1, w1, g1, b1, m1, v1, pf1, 256, 1600);
    conv_tf32_kernel<<<dim3( 4, 4, NFR), 256>>>(f2, w2, g2, b2, m2, v2, pf2, 512,  400);

    size_t sm0 = (size_t)(112 * 112 + 8 * NS) * sizeof(float);
    size_t sm1 = (size_t)( 56 *  56 + 8 * NS) * sizeof(float);
    size_t sm2 = (size_t)( 28 *  28 + 8 * NS) * sizeof(float);
    cudaFuncSetAttribute(corr_kernel<128, 80, 80, 4, 25>,
                         cudaFuncAttributeMaxDynamicSharedMemorySize, 65536);

    corr_kernel<128, 80, 80, 4, 25><<<dim3(128, NPAIR), 256, sm0>>>(pf0, mlpw, out, 0);
    corr_kernel<256, 40, 40, 2,  7><<<dim3(256, NPAIR), 256, sm1>>>(pf1, mlpw, out, 1024);
    corr_kernel<512, 20, 20, 1,  2><<<dim3(512, NPAIR), 256, sm2>>>(pf2, mlpw, out, 3072);
}

// round 4
// speedup vs baseline: 1.2805x; 1.1429x over previous
#include <cuda_runtime.h>
#include <math.h>
#include <stdint.h>

#define BB    4
#define TPP   4
#define TFF   2
#define NPAIR (BB*TFF)
#define RAD   4
#define NS    81
#define NFR   (BB*TPP)

// ---------------- scratch ---------------------------------------------------------
__device__ int   g_idx[NPAIR];
__device__ int   g_needed[NFR];
__device__ float g_pf0[(size_t)NFR * 128 * 6400];
__device__ float g_pf1[(size_t)NFR * 256 * 1600];
__device__ float g_pf2[(size_t)NFR * 512 * 400];
__device__ float g_w0h[128*128], g_w0l[128*128];
__device__ float g_w1h[256*256], g_w1l[256*256];
__device__ float g_w2h[512*512], g_w2l[512*512];

// ---------------- prep ------------------------------------------------------------
__global__ void prep_kernel(const int* __restrict__ pci, const int* __restrict__ fci)
{
    if (threadIdx.x != 0 || blockIdx.x != 0) return;
    for (int n = 0; n < NFR; n++) g_needed[n] = 0;
    for (int i = 0; i < BB; i++) {
        int p_pos = TPP - 2;
        for (int j = 0; j < TFF; j++) {
            int f_i = fci[i * TFF + j];
            while (p_pos >= 0) {
                if (p_pos == 0 || f_i < -pci[i * TPP + p_pos - 1]) {
                    int id = p_pos + i * TPP;
                    g_idx[i * TFF + j] = id;
                    g_needed[id] = 1;
                    break;
                }
                p_pos--;
            }
        }
        g_needed[i * TPP + (TPP - 1)] = 1;
    }
}

// ---------------- tf32 helpers ----------------------------------------------------
__device__ __forceinline__ uint32_t f2tf(float v)
{
    uint32_t r;
    asm("cvt.rna.tf32.f32 %0, %1;" : "=r"(r) : "f"(v));
    return r;
}

__global__ void wsplit_kernel(const float* __restrict__ w, float* __restrict__ wh,
                              float* __restrict__ wl, int n)
{
    int i = blockIdx.x * 256 + threadIdx.x;
    if (i < n) {
        float v = w[i];
        uint32_t h = f2tf(v);
        wh[i] = __uint_as_float(h);
        wl[i] = __uint_as_float(f2tf(v - __uint_as_float(h)));
    }
}

__device__ __forceinline__ void mma8(float* c, const uint32_t* a, const uint32_t* b)
{
    asm volatile(
        "mma.sync.aligned.m16n8k8.row.col.f32.tf32.tf32.f32 "
        "{%0,%1,%2,%3}, {%4,%5,%6,%7}, {%8,%9}, {%0,%1,%2,%3};"
        : "+f"(c[0]), "+f"(c[1]), "+f"(c[2]), "+f"(c[3])
        : "r"(a[0]), "r"(a[1]), "r"(a[2]), "r"(a[3]), "r"(b[0]), "r"(b[1]));
}

__device__ __forceinline__ float silu(float y) { return y / (1.0f + expf(-y)); }

__device__ __forceinline__ void cpa16(uint32_t daddr, const void* src)
{
    asm volatile("cp.async.ca.shared.global [%0], [%1], 16;" :: "r"(daddr), "l"(src));
}

// ---------------- conv: tf32 3-term, double-buffered cp.async pipeline ------------
// Block tile 128(d) x 128(p), K-chunk 16. 8 warps = 2(m) x 4(n), warp 64x32.
// dyn smem (uint32): AH[2][2560] AL[2][2560] BH[2][2176] BL[2][2176]
#define OF_AH 0
#define OF_AL 5120
#define OF_BH 10240
#define OF_BL 14592
#define DSMU  18944

__global__ void __launch_bounds__(256, 2) conv_tf32_kernel(
    const float* __restrict__ x,
    const float* __restrict__ whi, const float* __restrict__ wlo,
    const float* __restrict__ gg, const float* __restrict__ bbp,
    const float* __restrict__ mm, const float* __restrict__ vv,
    float* __restrict__ pf, int C, int HW)
{
    int n = blockIdx.z;
    if (!g_needed[n]) return;

    extern __shared__ uint32_t dsm[];
    const int tid  = threadIdx.x;
    const int lane = tid & 31;
    const int wid  = tid >> 5;
    const int p0   = blockIdx.x * 128;
    const int d0   = blockIdx.y * 128;
    const int m_off = (wid & 1) * 64;
    const int n_off = (wid >> 1) * 32;
    const int g  = lane >> 2;
    const int tg = lane & 3;

    // staging geometry
    const int arow = tid >> 2;            // A slot0 row (0..63), slot1 row+64
    const int ac4  = (tid & 3) * 4;
    const int brow = tid >> 5;            // B slot0 row (0..7), slot1 row+8
    const int bc4  = (tid & 31) * 4;
    const bool bok = (p0 + bc4 < HW);
    const float* xn = x + (size_t)n * C * HW + p0 + bc4;

    const uint32_t smbase = (uint32_t)__cvta_generic_to_shared(dsm);

    float acc[4][4][4];
#pragma unroll
    for (int mi = 0; mi < 4; mi++)
#pragma unroll
        for (int ni = 0; ni < 4; ni++)
#pragma unroll
            for (int r = 0; r < 4; r++) acc[mi][ni][r] = 0.f;

    const int NC = C >> 4;

    // ---- helpers as macros-in-code ----
    float4 xa, xb;
#define LDGX(KC)                                                                   \
    do {                                                                           \
        const float* b_ = xn + (size_t)((KC) * 16) * HW;                           \
        xa = bok ? *(const float4*)(b_ + (size_t)brow * HW)                        \
                 : make_float4(0.f, 0.f, 0.f, 0.f);                                \
        xb = bok ? *(const float4*)(b_ + (size_t)(brow + 8) * HW)                  \
                 : make_float4(0.f, 0.f, 0.f, 0.f);                                \
    } while (0)

#define CVTSTS(BUF)                                                               \
    do {                                                                           \
        float v0[4] = {xa.x, xa.y, xa.z, xa.w};                                    \
        float v1[4] = {xb.x, xb.y, xb.z, xb.w};                                    \
        uint32_t h0[4], l0[4], h1[4], l1[4];                                       \
        _Pragma("unroll")                                                          \
        for (int j = 0; j < 4; j++) {                                              \
            h0[j] = f2tf(v0[j]); l0[j] = f2tf(v0[j] - __uint_as_float(h0[j]));     \
            h1[j] = f2tf(v1[j]); l1[j] = f2tf(v1[j] - __uint_as_float(h1[j]));     \
        }                                                                          \
        uint32_t* bh = dsm + OF_BH + (BUF) * 2176;                                 \
        uint32_t* bl = dsm + OF_BL + (BUF) * 2176;                                 \
        *(uint4*)&bh[brow * 136 + bc4]       = make_uint4(h0[0], h0[1], h0[2], h0[3]); \
        *(uint4*)&bl[brow * 136 + bc4]       = make_uint4(l0[0], l0[1], l0[2], l0[3]); \
        *(uint4*)&bh[(brow + 8) * 136 + bc4] = make_uint4(h1[0], h1[1], h1[2], h1[3]); \
        *(uint4*)&bl[(brow + 8) * 136 + bc4] = make_uint4(l1[0], l1[1], l1[2], l1[3]); \
    } while (0)

#define CPA(BUF, KC)                                                              \
    do {                                                                           \
        int k0_ = (KC) * 16;                                                       \
        const float* sh0 = whi + (size_t)(d0 + arow) * C + k0_ + ac4;              \
        const float* sl0 = wlo + (size_t)(d0 + arow) * C + k0_ + ac4;              \
        const float* sh1 = sh0 + (size_t)64 * C;                                   \
        const float* sl1 = sl0 + (size_t)64 * C;                                   \
        uint32_t dh = smbase + (OF_AH + (BUF) * 2560) * 4;                         \
        uint32_t dl = smbase + (OF_AL + (BUF) * 2560) * 4;                         \
        cpa16(dh + (arow * 20 + ac4) * 4, sh0);                                    \
        cpa16(dh + ((arow + 64) * 20 + ac4) * 4, sh1);                             \
        cpa16(dl + (arow * 20 + ac4) * 4, sl0);                                    \
        cpa16(dl + ((arow + 64) * 20 + ac4) * 4, sl1);                             \
    } while (0)

    // ---- prologue ----
    LDGX(0);
    CVTSTS(0);
    CPA(0, 0);
    asm volatile("cp.async.commit_group;");
    if (NC > 1) LDGX(1);
    asm volatile("cp.async.wait_group 0;");
    __syncthreads();

    for (int kc = 0; kc < NC; kc++) {
        int cur = kc & 1, nxt = cur ^ 1;
        if (kc + 1 < NC) {
            CPA(nxt, kc + 1);
            asm volatile("cp.async.commit_group;");
            CVTSTS(nxt);
            if (kc + 2 < NC) LDGX(kc + 2);
        }
        // ---- MMA over buffer cur ----
        const uint32_t* AHc = dsm + OF_AH + cur * 2560;
        const uint32_t* ALc = dsm + OF_AL + cur * 2560;
        const uint32_t* BHc = dsm + OF_BH + cur * 2176;
        const uint32_t* BLc = dsm + OF_BL + cur * 2176;
#pragma unroll
        for (int ka = 0; ka < 2; ka++) {
            uint32_t bh[4][2], bl[4][2];
#pragma unroll
            for (int ni = 0; ni < 4; ni++) {
                int ab = (ka * 8 + tg) * 136 + n_off + ni * 8 + g;
                bh[ni][0] = BHc[ab]; bh[ni][1] = BHc[ab + 4 * 136];
                bl[ni][0] = BLc[ab]; bl[ni][1] = BLc[ab + 4 * 136];
            }
#pragma unroll
            for (int mi = 0; mi < 4; mi++) {
                int aa = (m_off + mi * 16 + g) * 20 + ka * 8 + tg;
                uint32_t ah[4] = {AHc[aa], AHc[aa + 160], AHc[aa + 4], AHc[aa + 164]};
                uint32_t al[4] = {ALc[aa], ALc[aa + 160], ALc[aa + 4], ALc[aa + 164]};
#pragma unroll
                for (int ni = 0; ni < 4; ni++) {
                    mma8(acc[mi][ni], ah, bh[ni]);
                    mma8(acc[mi][ni], ah, bl[ni]);
                    mma8(acc[mi][ni], al, bh[ni]);
                }
            }
        }
        asm volatile("cp.async.wait_group 0;");
        __syncthreads();
    }

    // ---- epilogue: BN + SiLU ----
#pragma unroll
    for (int mi = 0; mi < 4; mi++) {
        int r0 = d0 + m_off + mi * 16 + g;
        int r1 = r0 + 8;
        float sc0 = gg[r0] * (1.0f / sqrtf(vv[r0] + 1e-5f));
        float bi0 = bbp[r0] - mm[r0] * sc0;
        float sc1 = gg[r1] * (1.0f / sqrtf(vv[r1] + 1e-5f));
        float bi1 = bbp[r1] - mm[r1] * sc1;
        float* op0 = pf + ((size_t)n * C + r0) * HW;
        float* op1 = pf + ((size_t)n * C + r1) * HW;
#pragma unroll
        for (int ni = 0; ni < 4; ni++) {
            int p = p0 + n_off + ni * 8 + 2 * tg;
            if (p < HW) {
                *(float2*)(op0 + p) = make_float2(silu(acc[mi][ni][0] * sc0 + bi0),
                                                  silu(acc[mi][ni][1] * sc0 + bi0));
                *(float2*)(op1 + p) = make_float2(silu(acc[mi][ni][2] * sc1 + bi1),
                                                  silu(acc[mi][ni][3] * sc1 + bi1));
            }
        }
    }
}

// ---------------- correlation + softmax + mlp dot ---------------------------------
// thread owns NG groups of VEC consecutive pixels -> vector LDS, imm-offset dx.
template<int C, int H, int W, int STEP, int VEC, int NG>
__global__ void __launch_bounds__(256) corr_kernel(
    const float* __restrict__ pf, const float* __restrict__ mlpw,
    float* __restrict__ out, int out_off)
{
    constexpr int PAD = RAD * STEP;
    constexpr int W2  = W + 2 * PAD;
    constexpr int H2  = H + 2 * PAD;
    constexpr int HW  = H * W;

    extern __shared__ float sm[];
    float* f1p  = sm;
    float* wred = sm + H2 * W2;

    const int c    = blockIdx.x;
    const int n    = blockIdx.y;
    const int b    = n / TFF;
    const int n1   = b * TPP + (TPP - 1);
    const int n2   = g_idx[n];
    const int tid  = threadIdx.x;
    const int wid  = tid >> 5;
    const int lane = tid & 31;

    const float* f1g = pf + ((size_t)n1 * C + c) * HW;
    const float* f2g = pf + ((size_t)n2 * C + c) * HW;

    for (int q = tid; q < H2 * W2; q += 256) {
        int hh = q / W2 - PAD;
        int ww = q % W2 - PAD;
        float v = 0.f;
        if ((unsigned)hh < (unsigned)H && (unsigned)ww < (unsigned)W)
            v = f1g[hh * W + ww];
        f1p[q] = v;
    }

    float f2r[NG][VEC];
    int   basek[NG];
#pragma unroll
    for (int gI = 0; gI < NG; gI++) {
        int p = (tid + 256 * gI) * VEC;
        if (p < HW) {
            if (VEC == 4) {
                float4 v = *(const float4*)(f2g + p);
                f2r[gI][0] = v.x; f2r[gI][1] = v.y;
                if (VEC > 2) { f2r[gI][2] = v.z; f2r[gI][3] = v.w; }
            } else if (VEC == 2) {
                float2 v = *(const float2*)(f2g + p);
                f2r[gI][0] = v.x; f2r[gI][1] = v.y;
            } else {
                f2r[gI][0] = f2g[p];
            }
            basek[gI] = (p / W + PAD) * W2 + (p % W) + PAD;
        } else {
#pragma unroll
            for (int v = 0; v < VEC; v++) f2r[gI][v] = 0.f;
            basek[gI] = PAD * W2 + PAD;
        }
    }
    __syncthreads();

    for (int oy = 0; oy < 9; oy++) {
        int ro[NG];
        int dyo = (oy - RAD) * STEP * W2;
#pragma unroll
        for (int gI = 0; gI < NG; gI++) ro[gI] = basek[gI] + dyo;
#pragma unroll
        for (int ox = 0; ox < 9; ox++) {
            const int dxo = (ox - RAD) * STEP;
            float a0 = 0.f, a1 = 0.f;
#pragma unroll
            for (int gI = 0; gI < NG; gI++) {
                if (VEC == 4) {
                    float4 fv = *(const float4*)&f1p[ro[gI] + dxo];
                    a0 = fmaf(fv.x, f2r[gI][0], a0);
                    a1 = fmaf(fv.y, f2r[gI][1], a1);
                    a0 = fmaf(fv.z, f2r[gI][2], a0);
                    a1 = fmaf(fv.w, f2r[gI][3], a1);
                } else if (VEC == 2) {
                    float2 fv = *(const float2*)&f1p[ro[gI] + dxo];
                    a0 = fmaf(fv.x, f2r[gI][0], a0);
                    a1 = fmaf(fv.y, f2r[gI][1], a1);
                } else {
                    a0 = fmaf(f1p[ro[gI] + dxo], f2r[gI][0], a0);
                }
            }
            float v = a0 + a1;
#pragma unroll
            for (int o = 16; o; o >>= 1)
                v += __shfl_xor_sync(0xffffffffu, v, o);
            if (lane == 0) wred[wid * NS + oy * 9 + ox] = v;
        }
    }
    __syncthreads();

    if (tid < 32) {
        float v0, v1 = -1e30f, v2 = -1e30f;
        {
            float s0 = 0.f, s1 = 0.f, s2 = 0.f;
#pragma unroll
            for (int w = 0; w < 8; w++) {
                s0 += wred[w * NS + tid];
                if (tid + 32 < NS) s1 += wred[w * NS + tid + 32];
                if (tid + 64 < NS) s2 += wred[w * NS + tid + 64];
            }
            v0 = s0;
            if (tid + 32 < NS) v1 = s1;
            if (tid + 64 < NS) v2 = s2;
        }
        float mx = fmaxf(v0, fmaxf(v1, v2));
#pragma unroll
        for (int o = 16; o; o >>= 1)
            mx = fmaxf(mx, __shfl_xor_sync(0xffffffffu, mx, o));
        float e0 = expf(v0 - mx);
        float e1 = (tid + 32 < NS) ? expf(v1 - mx) : 0.f;
        float e2 = (tid + 64 < NS) ? expf(v2 - mx) : 0.f;
        float w0 = mlpw[tid];
        float w1 = (tid + 32 < NS) ? mlpw[tid + 32] : 0.f;
        float w2 = (tid + 64 < NS) ? mlpw[tid + 64] : 0.f;
        float ssum = e0 + e1 + e2;
        float dot  = e0 * w0 + e1 * w1 + e2 * w2;
#pragma unroll
        for (int o = 16; o; o >>= 1) {
            ssum += __shfl_xor_sync(0xffffffffu, ssum, o);
            dot  += __shfl_xor_sync(0xffffffffu, dot,  o);
        }
        if (tid == 0)
            out[out_off + n * C + c] = dot / ssum;
    }
}

// ---------------- launch ----------------------------------------------------------
extern "C" void kernel_launch(void* const* d_in, const int* in_sizes, int n_in,
                              void* d_out, int out_size)
{
    int map_sig [21] = {0,1,2, 3,4,5,6,7, 8,9,10,11,12, 13,14,15,16,17, 18,19,20};
    int map_dict[21] = {0,6,12, 1,2,3,4,5, 7,8,9,10,11, 13,14,15,16,17, 18,19,20};
    const int* map = (in_sizes[1] == 16384) ? map_dict : map_sig;

    const float* f0 = (const float*)d_in[map[0]];
    const float* f1 = (const float*)d_in[map[1]];
    const float* f2 = (const float*)d_in[map[2]];
    const float* w0 = (const float*)d_in[map[3]];
    const float* g0 = (const float*)d_in[map[4]];
    const float* b0 = (const float*)d_in[map[5]];
    const float* m0 = (const float*)d_in[map[6]];
    const float* v0 = (const float*)d_in[map[7]];
    const float* w1 = (const float*)d_in[map[8]];
    const float* g1 = (const float*)d_in[map[9]];
    const float* b1 = (const float*)d_in[map[10]];
    const float* m1 = (const float*)d_in[map[11]];
    const float* v1 = (const float*)d_in[map[12]];
    const float* w2 = (const float*)d_in[map[13]];
    const float* g2 = (const float*)d_in[map[14]];
    const float* b2 = (const float*)d_in[map[15]];
    const float* m2 = (const float*)d_in[map[16]];
    const float* v2 = (const float*)d_in[map[17]];
    const float* mlpw = (const float*)d_in[map[18]];
    const int*   pci  = (const int*)d_in[map[19]];
    const int*   fci  = (const int*)d_in[map[20]];
    float* out = (float*)d_out;

    void *pv;
    cudaGetSymbolAddress(&pv, g_pf0);  float* pf0 = (float*)pv;
    cudaGetSymbolAddress(&pv, g_pf1);  float* pf1 = (float*)pv;
    cudaGetSymbolAddress(&pv, g_pf2);  float* pf2 = (float*)pv;
    cudaGetSymbolAddress(&pv, g_w0h);  float* w0h = (float*)pv;
    cudaGetSymbolAddress(&pv, g_w0l);  float* w0l = (float*)pv;
    cudaGetSymbolAddress(&pv, g_w1h);  float* w1h = (float*)pv;
    cudaGetSymbolAddress(&pv, g_w1l);  float* w1l = (float*)pv;
    cudaGetSymbolAddress(&pv, g_w2h);  float* w2h = (float*)pv;
    cudaGetSymbolAddress(&pv, g_w2l);  float* w2l = (float*)pv;

    prep_kernel<<<1, 1>>>(pci, fci);
    wsplit_kernel<<<(128*128 + 255) / 256, 256>>>(w0, w0h, w0l, 128*128);
    wsplit_kernel<<<(256*256 + 255) / 256, 256>>>(w1, w1h, w1l, 256*256);
    wsplit_kernel<<<(512*512 + 255) / 256, 256>>>(w2, w2h, w2l, 512*512);

    const int DSMB = DSMU * 4;   // 75776 bytes
    cudaFuncSetAttribute(conv_tf32_kernel,
                         cudaFuncAttributeMaxDynamicSharedMemorySize, DSMB);

    conv_tf32_kernel<<<dim3(50, 1, NFR), 256, DSMB>>>(f0, w0h, w0l, g0, b0, m0, v0, pf0, 128, 6400);
    conv_tf32_kernel<<<dim3(13, 2, NFR), 256, DSMB>>>(f1, w1h, w1l, g1, b1, m1, v1, pf1, 256, 1600);
    conv_tf32_kernel<<<dim3( 4, 4, NFR), 256, DSMB>>>(f2, w2h, w2l, g2, b2, m2, v2, pf2, 512,  400);

    size_t sm0 = (size_t)(112 * 112 + 8 * NS) * sizeof(float);
    size_t sm1 = (size_t)( 56 *  56 + 8 * NS) * sizeof(float);
    size_t sm2 = (size_t)( 28 *  28 + 8 * NS) * sizeof(float);
    cudaFuncSetAttribute((const void*)corr_kernel<128, 80, 80, 4, 4, 7>,
                         cudaFuncAttributeMaxDynamicSharedMemorySize, 65536);

    corr_kernel<128, 80, 80, 4, 4, 7><<<dim3(128, NPAIR), 256, sm0>>>(pf0, mlpw, out, 0);
    corr_kernel<256, 40, 40, 2, 2, 4><<<dim3(256, NPAIR), 256, sm1>>>(pf1, mlpw, out, 1024);
    corr_kernel<512, 20, 20, 1, 1, 2><<<dim3(512, NPAIR), 256, sm2>>>(pf2, mlpw, out, 3072);
}

// round 5
// speedup vs baseline: 1.7402x; 1.3591x over previous
#include <cuda_runtime.h>
#include <math.h>
#include <stdint.h>

#define BB    4
#define TPP   4
#define TFF   2
#define NPAIR (BB*TFF)
#define RAD   4
#define NS    81
#define NFR   (BB*TPP)

// ---------------- scratch ---------------------------------------------------------
__device__ int   g_idx[NPAIR];
__device__ int   g_needed[NFR];
__device__ float g_pf0[(size_t)NFR * 128 * 6400];
__device__ float g_pf1[(size_t)NFR * 256 * 1600];
__device__ float g_pf2[(size_t)NFR * 512 * 400];
__device__ float g_w0h[128*128], g_w0l[128*128];
__device__ float g_w1h[256*256], g_w1l[256*256];
__device__ float g_w2h[512*512], g_w2l[512*512];

// ---------------- prep ------------------------------------------------------------
__global__ void prep_kernel(const int* __restrict__ pci, const int* __restrict__ fci)
{
    if (threadIdx.x != 0 || blockIdx.x != 0) return;
    for (int n = 0; n < NFR; n++) g_needed[n] = 0;
    for (int i = 0; i < BB; i++) {
        int p_pos = TPP - 2;
        for (int j = 0; j < TFF; j++) {
            int f_i = fci[i * TFF + j];
            while (p_pos >= 0) {
                if (p_pos == 0 || f_i < -pci[i * TPP + p_pos - 1]) {
                    int id = p_pos + i * TPP;
                    g_idx[i * TFF + j] = id;
                    g_needed[id] = 1;
                    break;
                }
                p_pos--;
            }
        }
        g_needed[i * TPP + (TPP - 1)] = 1;
    }
}

// ---------------- tf32 helpers ----------------------------------------------------
__device__ __forceinline__ uint32_t f2tf(float v)
{
    uint32_t r;
    asm("cvt.rna.tf32.f32 %0, %1;" : "=r"(r) : "f"(v));
    return r;
}

__global__ void wsplit_kernel(const float* __restrict__ w, float* __restrict__ wh,
                              float* __restrict__ wl, int n)
{
    int i = blockIdx.x * 256 + threadIdx.x;
    if (i < n) {
        float v = w[i];
        uint32_t h = f2tf(v);
        wh[i] = __uint_as_float(h);
        wl[i] = __uint_as_float(f2tf(v - __uint_as_float(h)));
    }
}

__device__ __forceinline__ void mma8(float* c, const uint32_t* a, const uint32_t* b)
{
    asm volatile(
        "mma.sync.aligned.m16n8k8.row.col.f32.tf32.tf32.f32 "
        "{%0,%1,%2,%3}, {%4,%5,%6,%7}, {%8,%9}, {%0,%1,%2,%3};"
        : "+f"(c[0]), "+f"(c[1]), "+f"(c[2]), "+f"(c[3])
        : "r"(a[0]), "r"(a[1]), "r"(a[2]), "r"(a[3]), "r"(b[0]), "r"(b[1]));
}

__device__ __forceinline__ float silu(float y) { return y / (1.0f + expf(-y)); }

__device__ __forceinline__ void cpa16(uint32_t daddr, const void* src)
{
    asm volatile("cp.async.ca.shared.global [%0], [%1], 16;" :: "r"(daddr), "l"(src));
}

// ---------------- merged conv: tf32 3-term, cp.async double buffer ---------------
#define OF_AH 0
#define OF_AL 5120
#define OF_BH 10240
#define OF_BL 14592
#define DSMU  18944

struct ConvAll {
    const float* x[3];
    const float* wh[3];
    const float* wl[3];
    const float* gg[3];
    const float* bb[3];
    const float* mm[3];
    const float* vv[3];
    float*       pf[3];
};

__global__ void __launch_bounds__(256, 2) conv_tf32_kernel(ConvAll P)
{
    int n = blockIdx.z;
    if (!g_needed[n]) return;

    // decode level / tile
    int bx = blockIdx.x, lvl, p0, d0;
    if (bx < 50)      { lvl = 0; p0 = bx * 128; d0 = 0; }
    else if (bx < 76) { int r = bx - 50; lvl = 1; p0 = (r % 13) * 128; d0 = (r / 13) * 128; }
    else              { int r = bx - 76; lvl = 2; p0 = (r & 3) * 128;  d0 = (r >> 2) * 128; }
    const int C  = 128 << lvl;
    const int HW = 6400 >> (2 * lvl);
    const float* x   = P.x[lvl];
    const float* whi = P.wh[lvl];
    const float* wlo = P.wl[lvl];

    extern __shared__ uint32_t dsm[];
    const int tid  = threadIdx.x;
    const int lane = tid & 31;
    const int wid  = tid >> 5;
    const int m_off = (wid & 1) * 64;
    const int n_off = (wid >> 1) * 32;
    const int g  = lane >> 2;
    const int tg = lane & 3;

    const int arow = tid >> 2;
    const int ac4  = (tid & 3) * 4;
    const int brow = tid >> 5;
    const int bc4  = (tid & 31) * 4;
    const bool bok = (p0 + bc4 < HW);
    const float* xn = x + (size_t)n * C * HW + p0 + bc4;

    const uint32_t smbase = (uint32_t)__cvta_generic_to_shared(dsm);

    float acc[4][4][4];
#pragma unroll
    for (int mi = 0; mi < 4; mi++)
#pragma unroll
        for (int ni = 0; ni < 4; ni++)
#pragma unroll
            for (int r = 0; r < 4; r++) acc[mi][ni][r] = 0.f;

    const int NC = C >> 4;
    float4 xa, xb;

#define LDGX(KC)                                                                   \
    do {                                                                           \
        const float* b_ = xn + (size_t)((KC) * 16) * HW;                           \
        xa = bok ? *(const float4*)(b_ + (size_t)brow * HW)                        \
                 : make_float4(0.f, 0.f, 0.f, 0.f);                                \
        xb = bok ? *(const float4*)(b_ + (size_t)(brow + 8) * HW)                  \
                 : make_float4(0.f, 0.f, 0.f, 0.f);                                \
    } while (0)

#define CVTSTS(BUF)                                                               \
    do {                                                                           \
        float v0[4] = {xa.x, xa.y, xa.z, xa.w};                                    \
        float v1[4] = {xb.x, xb.y, xb.z, xb.w};                                    \
        uint32_t h0[4], l0[4], h1[4], l1[4];                                       \
        _Pragma("unroll")                                                          \
        for (int j = 0; j < 4; j++) {                                              \
            h0[j] = f2tf(v0[j]); l0[j] = f2tf(v0[j] - __uint_as_float(h0[j]));     \
            h1[j] = f2tf(v1[j]); l1[j] = f2tf(v1[j] - __uint_as_float(h1[j]));     \
        }                                                                          \
        uint32_t* bh = dsm + OF_BH + (BUF) * 2176;                                 \
        uint32_t* bl = dsm + OF_BL + (BUF) * 2176;                                 \
        *(uint4*)&bh[brow * 136 + bc4]       = make_uint4(h0[0], h0[1], h0[2], h0[3]); \
        *(uint4*)&bl[brow * 136 + bc4]       = make_uint4(l0[0], l0[1], l0[2], l0[3]); \
        *(uint4*)&bh[(brow + 8) * 136 + bc4] = make_uint4(h1[0], h1[1], h1[2], h1[3]); \
        *(uint4*)&bl[(brow + 8) * 136 + bc4] = make_uint4(l1[0], l1[1], l1[2], l1[3]); \
    } while (0)

#define CPA(BUF, KC)                                                              \
    do {                                                                           \
        int k0_ = (KC) * 16;                                                       \
        const float* sh0 = whi + (size_t)(d0 + arow) * C + k0_ + ac4;              \
        const float* sl0 = wlo + (size_t)(d0 + arow) * C + k0_ + ac4;              \
        const float* sh1 = sh0 + (size_t)64 * C;                                   \
        const float* sl1 = sl0 + (size_t)64 * C;                                   \
        uint32_t dh = smbase + (OF_AH + (BUF) * 2560) * 4;                         \
        uint32_t dl = smbase + (OF_AL + (BUF) * 2560) * 4;                         \
        cpa16(dh + (arow * 20 + ac4) * 4, sh0);                                    \
        cpa16(dh + ((arow + 64) * 20 + ac4) * 4, sh1);                             \
        cpa16(dl + (arow * 20 + ac4) * 4, sl0);                                    \
        cpa16(dl + ((arow + 64) * 20 + ac4) * 4, sl1);                             \
    } while (0)

    LDGX(0);
    CVTSTS(0);
    CPA(0, 0);
    asm volatile("cp.async.commit_group;");
    if (NC > 1) LDGX(1);
    asm volatile("cp.async.wait_group 0;");
    __syncthreads();

    for (int kc = 0; kc < NC; kc++) {
        int cur = kc & 1, nxt = cur ^ 1;
        if (kc + 1 < NC) {
            CPA(nxt, kc + 1);
            asm volatile("cp.async.commit_group;");
            CVTSTS(nxt);
            if (kc + 2 < NC) LDGX(kc + 2);
        }
        const uint32_t* AHc = dsm + OF_AH + cur * 2560;
        const uint32_t* ALc = dsm + OF_AL + cur * 2560;
        const uint32_t* BHc = dsm + OF_BH + cur * 2176;
        const uint32_t* BLc = dsm + OF_BL + cur * 2176;
#pragma unroll
        for (int ka = 0; ka < 2; ka++) {
            uint32_t bh[4][2], bl[4][2];
#pragma unroll
            for (int ni = 0; ni < 4; ni++) {
                int ab = (ka * 8 + tg) * 136 + n_off + ni * 8 + g;
                bh[ni][0] = BHc[ab]; bh[ni][1] = BHc[ab + 4 * 136];
                bl[ni][0] = BLc[ab]; bl[ni][1] = BLc[ab + 4 * 136];
            }
#pragma unroll
            for (int mi = 0; mi < 4; mi++) {
                int aa = (m_off + mi * 16 + g) * 20 + ka * 8 + tg;
                uint32_t ah[4] = {AHc[aa], AHc[aa + 160], AHc[aa + 4], AHc[aa + 164]};
                uint32_t al[4] = {ALc[aa], ALc[aa + 160], ALc[aa + 4], ALc[aa + 164]};
#pragma unroll
                for (int ni = 0; ni < 4; ni++) {
                    mma8(acc[mi][ni], ah, bh[ni]);
                    mma8(acc[mi][ni], ah, bl[ni]);
                    mma8(acc[mi][ni], al, bh[ni]);
                }
            }
        }
        asm volatile("cp.async.wait_group 0;");
        __syncthreads();
    }

    const float* gg  = P.gg[lvl];
    const float* bbp = P.bb[lvl];
    const float* mm  = P.mm[lvl];
    const float* vv  = P.vv[lvl];
    float*       pf  = P.pf[lvl];
#pragma unroll
    for (int mi = 0; mi < 4; mi++) {
        int r0 = d0 + m_off + mi * 16 + g;
        int r1 = r0 + 8;
        float sc0 = gg[r0] * (1.0f / sqrtf(vv[r0] + 1e-5f));
        float bi0 = bbp[r0] - mm[r0] * sc0;
        float sc1 = gg[r1] * (1.0f / sqrtf(vv[r1] + 1e-5f));
        float bi1 = bbp[r1] - mm[r1] * sc1;
        float* op0 = pf + ((size_t)n * C + r0) * HW;
        float* op1 = pf + ((size_t)n * C + r1) * HW;
#pragma unroll
        for (int ni = 0; ni < 4; ni++) {
            int p = p0 + n_off + ni * 8 + 2 * tg;
            if (p < HW) {
                *(float2*)(op0 + p) = make_float2(silu(acc[mi][ni][0] * sc0 + bi0),
                                                  silu(acc[mi][ni][1] * sc0 + bi0));
                *(float2*)(op1 + p) = make_float2(silu(acc[mi][ni][2] * sc1 + bi1),
                                                  silu(acc[mi][ni][3] * sc1 + bi1));
            }
        }
    }
}

// ---------------- corr v2: pair-merged, register-window for STEP<=2 ---------------
// block = (channel c, batch b); handles both future pairs of b (shared f1 plane).
// WINL=0 : strided-LDS scheme (STEP=4). WINL>0 : per-oy register window.
template<int C, int H, int W, int STEP, int NG, int NT, int WINL>
__global__ void __launch_bounds__(NT) corr2_kernel(
    const float* __restrict__ pf, const float* __restrict__ mlpw,
    float* __restrict__ out, int out_off)
{
    constexpr int PAD = RAD * STEP;
    constexpr int W2  = W + 2 * PAD;
    constexpr int H2  = H + 2 * PAD;
    constexpr int HW  = H * W;
    constexpr int NW  = NT / 32;

    extern __shared__ float sm[];
    float* f1p  = sm;
    float* wred = sm + H2 * W2;    // [2][NW][NS]

    const int c    = blockIdx.x;
    const int b    = blockIdx.y;
    const int n1   = b * TPP + (TPP - 1);
    const int n2a  = g_idx[b * TFF + 0];
    const int n2b  = g_idx[b * TFF + 1];
    const int tid  = threadIdx.x;
    const int wid  = tid >> 5;
    const int lane = tid & 31;

    const float* f1g = pf + ((size_t)n1  * C + c) * HW;
    const float* f2a = pf + ((size_t)n2a * C + c) * HW;
    const float* f2b = pf + ((size_t)n2b * C + c) * HW;

    for (int q = tid; q < H2 * W2; q += NT) {
        int hh = q / W2 - PAD;
        int ww = q % W2 - PAD;
        float v = 0.f;
        if ((unsigned)hh < (unsigned)H && (unsigned)ww < (unsigned)W)
            v = f1g[hh * W + ww];
        f1p[q] = v;
    }

    float fra[NG][4], frb[NG][4];
    int   basek[NG];
#pragma unroll
    for (int gi = 0; gi < NG; gi++) {
        int p = (tid + NT * gi) * 4;
        if (p < HW) {
            float4 va = *(const float4*)(f2a + p);
            float4 vb = *(const float4*)(f2b + p);
            fra[gi][0] = va.x; fra[gi][1] = va.y; fra[gi][2] = va.z; fra[gi][3] = va.w;
            frb[gi][0] = vb.x; frb[gi][1] = vb.y; frb[gi][2] = vb.z; frb[gi][3] = vb.w;
            basek[gi] = (p / W + PAD) * W2 + (p % W) + PAD;
        } else {
#pragma unroll
            for (int v = 0; v < 4; v++) { fra[gi][v] = 0.f; frb[gi][v] = 0.f; }
            basek[gi] = PAD * W2 + PAD;
        }
    }
    __syncthreads();

    if (WINL == 0) {
        // strided scheme: one LDS.128 per group per offset, 8 FFMA per load
        for (int oy = 0; oy < 9; oy++) {
            int ro[NG];
            int dyo = (oy - RAD) * STEP * W2;
#pragma unroll
            for (int gi = 0; gi < NG; gi++) ro[gi] = basek[gi] + dyo;
#pragma unroll
            for (int ox = 0; ox < 9; ox++) {
                const int dxo = (ox - RAD) * STEP;
                float a0 = 0.f, a1 = 0.f, b0 = 0.f, b1 = 0.f;
#pragma unroll
                for (int gi = 0; gi < NG; gi++) {
                    float4 fv = *(const float4*)&f1p[ro[gi] + dxo];
                    a0 = fmaf(fv.x, fra[gi][0], a0);
                    a1 = fmaf(fv.y, fra[gi][1], a1);
                    a0 = fmaf(fv.z, fra[gi][2], a0);
                    a1 = fmaf(fv.w, fra[gi][3], a1);
                    b0 = fmaf(fv.x, frb[gi][0], b0);
                    b1 = fmaf(fv.y, frb[gi][1], b1);
                    b0 = fmaf(fv.z, frb[gi][2], b0);
                    b1 = fmaf(fv.w, frb[gi][3], b1);
                }
                float va = a0 + a1, vb = b0 + b1;
#pragma unroll
                for (int o = 16; o; o >>= 1) {
                    va += __shfl_xor_sync(0xffffffffu, va, o);
                    vb += __shfl_xor_sync(0xffffffffu, vb, o);
                }
                if (lane == 0) {
                    wred[(0 * NW + wid) * NS + oy * 9 + ox] = va;
                    wred[(1 * NW + wid) * NS + oy * 9 + ox] = vb;
                }
            }
        }
    } else {
        // window scheme: per oy load WINL floats, all 9 ox from registers
        for (int oy = 0; oy < 9; oy++) {
            int dyo = (oy - RAD) * STEP * W2;
            float aA[9], aB[9];
#pragma unroll
            for (int ox = 0; ox < 9; ox++) { aA[ox] = 0.f; aB[ox] = 0.f; }
#pragma unroll
            for (int gi = 0; gi < NG; gi++) {
                const float* wp = &f1p[basek[gi] + dyo - 4 * STEP];
                float win[WINL > 0 ? WINL : 1];
#pragma unroll
                for (int t = 0; t < WINL / 4; t++) {
                    float4 v = *(const float4*)(wp + 4 * t);
                    win[4 * t] = v.x; win[4 * t + 1] = v.y;
                    win[4 * t + 2] = v.z; win[4 * t + 3] = v.w;
                }
#pragma unroll
                for (int ox = 0; ox < 9; ox++) {
#pragma unroll
                    for (int j = 0; j < 4; j++) {
                        aA[ox] = fmaf(win[STEP * ox + j], fra[gi][j], aA[ox]);
                        aB[ox] = fmaf(win[STEP * ox + j], frb[gi][j], aB[ox]);
                    }
                }
            }
#pragma unroll
            for (int ox = 0; ox < 9; ox++) {
                float va = aA[ox], vb = aB[ox];
#pragma unroll
                for (int o = 16; o; o >>= 1) {
                    va += __shfl_xor_sync(0xffffffffu, va, o);
                    vb += __shfl_xor_sync(0xffffffffu, vb, o);
                }
                if (lane == 0) {
                    wred[(0 * NW + wid) * NS + oy * 9 + ox] = va;
                    wred[(1 * NW + wid) * NS + oy * 9 + ox] = vb;
                }
            }
        }
    }
    __syncthreads();

    // final: warp 0 -> pair 0, warp 1 -> pair 1
    if (tid < 64) {
        int q = tid >> 5, l = tid & 31;
        const float* wr = wred + q * NW * NS;
        float v0, v1 = -1e30f, v2 = -1e30f;
        {
            float s0 = 0.f, s1 = 0.f, s2 = 0.f;
#pragma unroll
            for (int w = 0; w < NW; w++) {
                s0 += wr[w * NS + l];
                if (l + 32 < NS) s1 += wr[w * NS + l + 32];
                if (l + 64 < NS) s2 += wr[w * NS + l + 64];
            }
            v0 = s0;
            if (l + 32 < NS) v1 = s1;
            if (l + 64 < NS) v2 = s2;
        }
        float mx = fmaxf(v0, fmaxf(v1, v2));
#pragma unroll
        for (int o = 16; o; o >>= 1)
            mx = fmaxf(mx, __shfl_xor_sync(0xffffffffu, mx, o));
        float e0 = expf(v0 - mx);
        float e1 = (l + 32 < NS) ? expf(v1 - mx) : 0.f;
        float e2 = (l + 64 < NS) ? expf(v2 - mx) : 0.f;
        float w0 = mlpw[l];
        float w1 = (l + 32 < NS) ? mlpw[l + 32] : 0.f;
        float w2 = (l + 64 < NS) ? mlpw[l + 64] : 0.f;
        float ssum = e0 + e1 + e2;
        float dot  = e0 * w0 + e1 * w1 + e2 * w2;
#pragma unroll
        for (int o = 16; o; o >>= 1) {
            ssum += __shfl_xor_sync(0xffffffffu, ssum, o);
            dot  += __shfl_xor_sync(0xffffffffu, dot,  o);
        }
        if (l == 0)
            out[out_off + (b * TFF + q) * C + c] = dot / ssum;
    }
}

// ---------------- launch ----------------------------------------------------------
extern "C" void kernel_launch(void* const* d_in, const int* in_sizes, int n_in,
                              void* d_out, int out_size)
{
    int map_sig [21] = {0,1,2, 3,4,5,6,7, 8,9,10,11,12, 13,14,15,16,17, 18,19,20};
    int map_dict[21] = {0,6,12, 1,2,3,4,5, 7,8,9,10,11, 13,14,15,16,17, 18,19,20};
    const int* map = (in_sizes[1] == 16384) ? map_dict : map_sig;

    const float* mlpw = (const float*)d_in[map[18]];
    const int*   pci  = (const int*)d_in[map[19]];
    const int*   fci  = (const int*)d_in[map[20]];
    float* out = (float*)d_out;

    void* pv;
    cudaGetSymbolAddress(&pv, g_pf0);  float* pf0 = (float*)pv;
    cudaGetSymbolAddress(&pv, g_pf1);  float* pf1 = (float*)pv;
    cudaGetSymbolAddress(&pv, g_pf2);  float* pf2 = (float*)pv;
    cudaGetSymbolAddress(&pv, g_w0h);  float* w0h = (float*)pv;
    cudaGetSymbolAddress(&pv, g_w0l);  float* w0l = (float*)pv;
    cudaGetSymbolAddress(&pv, g_w1h);  float* w1h = (float*)pv;
    cudaGetSymbolAddress(&pv, g_w1l);  float* w1l = (float*)pv;
    cudaGetSymbolAddress(&pv, g_w2h);  float* w2h = (float*)pv;
    cudaGetSymbolAddress(&pv, g_w2l);  float* w2l = (float*)pv;

    prep_kernel<<<1, 1>>>(pci, fci);
    wsplit_kernel<<<(128*128 + 255) / 256, 256>>>((const float*)d_in[map[3]],  w0h, w0l, 128*128);
    wsplit_kernel<<<(256*256 + 255) / 256, 256>>>((const float*)d_in[map[8]],  w1h, w1l, 256*256);
    wsplit_kernel<<<(512*512 + 255) / 256, 256>>>((const float*)d_in[map[13]], w2h, w2l, 512*512);

    ConvAll P;
    P.x[0] = (const float*)d_in[map[0]];  P.x[1] = (const float*)d_in[map[1]];  P.x[2] = (const float*)d_in[map[2]];
    P.wh[0] = w0h; P.wh[1] = w1h; P.wh[2] = w2h;
    P.wl[0] = w0l; P.wl[1] = w1l; P.wl[2] = w2l;
    P.gg[0] = (const float*)d_in[map[4]];  P.gg[1] = (const float*)d_in[map[9]];   P.gg[2] = (const float*)d_in[map[14]];
    P.bb[0] = (const float*)d_in[map[5]];  P.bb[1] = (const float*)d_in[map[10]];  P.bb[2] = (const float*)d_in[map[15]];
    P.mm[0] = (const float*)d_in[map[6]];  P.mm[1] = (const float*)d_in[map[11]];  P.mm[2] = (const float*)d_in[map[16]];
    P.vv[0] = (const float*)d_in[map[7]];  P.vv[1] = (const float*)d_in[map[12]];  P.vv[2] = (const float*)d_in[map[17]];
    P.pf[0] = pf0; P.pf[1] = pf1; P.pf[2] = pf2;

    const int DSMB = DSMU * 4;
    cudaFuncSetAttribute(conv_tf32_kernel,
                         cudaFuncAttributeMaxDynamicSharedMemorySize, DSMB);
    conv_tf32_kernel<<<dim3(92, 1, NFR), 256, DSMB>>>(P);

    size_t sm0 = (size_t)(112 * 112 + 2 * 8 * NS) * sizeof(float);  // ~55.4 KB
    size_t sm1 = (size_t)( 56 *  56 + 2 * 8 * NS) * sizeof(float);
    size_t sm2 = (size_t)( 28 *  28 + 2 * 4 * NS) * sizeof(float);
    cudaFuncSetAttribute((const void*)corr2_kernel<128, 80, 80, 4, 7, 256, 0>,
                         cudaFuncAttributeMaxDynamicSharedMemorySize, 65536);

    corr2_kernel<128, 80, 80, 4, 7, 256,  0><<<dim3(128, BB), 256, sm0>>>(pf0, mlpw, out, 0);
    corr2_kernel<256, 40, 40, 2, 2, 256, 20><<<dim3(256, BB), 256, sm1>>>(pf1, mlpw, out, 1024);
    corr2_kernel<512, 20, 20, 1, 1, 128, 12><<<dim3(512, BB), 128, sm2>>>(pf2, mlpw, out, 3072);
}

// round 7
// speedup vs baseline: 1.8780x; 1.0792x over previous
#include <cuda_runtime.h>
#include <cuda_bf16.h>
#include <math.h>
#include <stdint.h>

#define BB    4
#define TPP   4
#define TFF   2
#define NPAIR (BB*TFF)
#define RAD   4
#define NS    81
#define NFR   (BB*TPP)

// ---------------- scratch ---------------------------------------------------------
__device__ int   g_idx[NPAIR];
__device__ int   g_needed[NFR];
__device__ float g_pf0[(size_t)NFR * 128 * 6400];
__device__ float g_pf1[(size_t)NFR * 256 * 1600];
__device__ float g_pf2[(size_t)NFR * 512 * 400];
// bf16 split weights [d][c]
__device__ __nv_bfloat16 g_w0a[128*128],  g_w0b[128*128];
__device__ __nv_bfloat16 g_w1a[256*256],  g_w1b[256*256];
__device__ __nv_bfloat16 g_w2a[512*512],  g_w2b[512*512];
// bf16 split features, layout [frame][c][p padded]
__device__ __nv_bfloat16 g_x0a[(size_t)NFR*128*6400], g_x0b[(size_t)NFR*128*6400];
__device__ __nv_bfloat16 g_x1a[(size_t)NFR*256*1664], g_x1b[(size_t)NFR*256*1664];
__device__ __nv_bfloat16 g_x2a[(size_t)NFR*512*512],  g_x2b[(size_t)NFR*512*512];

// ---------------- prep ------------------------------------------------------------
__global__ void prep_kernel(const int* __restrict__ pci, const int* __restrict__ fci)
{
    if (threadIdx.x != 0 || blockIdx.x != 0) return;
    for (int n = 0; n < NFR; n++) g_needed[n] = 0;
    for (int i = 0; i < BB; i++) {
        int p_pos = TPP - 2;
        for (int j = 0; j < TFF; j++) {
            int f_i = fci[i * TFF + j];
            while (p_pos >= 0) {
                if (p_pos == 0 || f_i < -pci[i * TPP + p_pos - 1]) {
                    int id = p_pos + i * TPP;
                    g_idx[i * TFF + j] = id;
                    g_needed[id] = 1;
                    break;
                }
                p_pos--;
            }
        }
        g_needed[i * TPP + (TPP - 1)] = 1;
    }
}

// ---------------- split kernels ---------------------------------------------------
__global__ void wsplit_kernel(const float* __restrict__ w,
                              __nv_bfloat16* __restrict__ wa,
                              __nv_bfloat16* __restrict__ wb, int nElems)
{
    int i = blockIdx.x * 256 + threadIdx.x;
    if (i < nElems) {
        float v = w[i];
        __nv_bfloat16 h = __float2bfloat16(v);
        wa[i] = h;
        wb[i] = __float2bfloat16(v - __bfloat162float(h));
    }
}

__global__ void xsplit_kernel(const float* __restrict__ x,
                              __nv_bfloat16* __restrict__ xa,
                              __nv_bfloat16* __restrict__ xb,
                              int C, int HW, int HWpad)
{
    int n = blockIdx.z;
    if (!g_needed[n]) return;
    int i = blockIdx.x * 256 + threadIdx.x;
    int tot = C * HWpad;
    if (i >= tot) return;
    int c = i / HWpad, p = i - c * HWpad;
    float v = (p < HW) ? x[(size_t)n * C * HW + (size_t)c * HW + p] : 0.f;
    __nv_bfloat16 h = __float2bfloat16(v);
    size_t o = (size_t)n * tot + i;
    xa[o] = h;
    xb[o] = __float2bfloat16(v - __bfloat162float(h));
}

// ---------------- mma.sync bf16 helpers -------------------------------------------
__device__ __forceinline__ uint32_t smem_u32(const void* p)
{
    uint32_t a;
    asm("{ .reg .u64 t; cvta.to.shared.u64 t, %1; cvt.u32.u64 %0, t; }" : "=r"(a) : "l"(p));
    return a;
}

__device__ __forceinline__ void ldm_x4(uint32_t* r, uint32_t addr)
{
    asm volatile("ldmatrix.sync.aligned.m8n8.x4.shared.b16 {%0,%1,%2,%3}, [%4];"
                 : "=r"(r[0]), "=r"(r[1]), "=r"(r[2]), "=r"(r[3]) : "r"(addr));
}

__device__ __forceinline__ void ldm_x4t(uint32_t* r, uint32_t addr)
{
    asm volatile("ldmatrix.sync.aligned.m8n8.x4.trans.shared.b16 {%0,%1,%2,%3}, [%4];"
                 : "=r"(r[0]), "=r"(r[1]), "=r"(r[2]), "=r"(r[3]) : "r"(addr));
}

__device__ __forceinline__ void mma16(float* c, const uint32_t* a, const uint32_t* b)
{
    asm volatile(
        "mma.sync.aligned.m16n8k16.row.col.f32.bf16.bf16.f32 "
        "{%0,%1,%2,%3}, {%4,%5,%6,%7}, {%8,%9}, {%0,%1,%2,%3};"
        : "+f"(c[0]), "+f"(c[1]), "+f"(c[2]), "+f"(c[3])
        : "r"(a[0]), "r"(a[1]), "r"(a[2]), "r"(a[3]), "r"(b[0]), "r"(b[1]));
}

__device__ __forceinline__ void cpa16(uint32_t dst, const void* src)
{
    asm volatile("cp.async.ca.shared.global [%0], [%1], 16;" :: "r"(dst), "l"(src));
}

__device__ __forceinline__ float silu(float y) { return y / (1.0f + expf(-y)); }

// ---------------- conv: bf16 3-term mma.sync, double-buffered ---------------------
// Block tile 128(d) x 128(p), K-chunk 32 bf16. 8 warps = 2(m) x 4(n), warp 64x32.
// smem buffer (32 KB): Ah@0 [128][32]b16, Al@8192, Bh@16384 [32][128]b16, Bl@24576.
// A swizzle: off = row*64 + ((cb ^ ((row>>1)&3))<<4)   (cb = 16B chunk, 4 per row)
// B swizzle: off = row*256 + ((nb ^ (row&7))<<4)       (nb = 16B chunk, 16 per row)
struct ConvTC {
    const __nv_bfloat16 *wa[3], *wb[3], *xa[3], *xb[3];
    const float *gg[3], *bb[3], *mm[3], *vv[3];
    float *pf[3];
};

__global__ void __launch_bounds__(256, 2) conv_bf16_kernel(ConvTC P)
{
    int n = blockIdx.z;
    if (!g_needed[n]) return;

    int bx = blockIdx.x, lvl, p0, d0;
    if (bx < 50)      { lvl = 0; p0 = bx * 128; d0 = 0; }
    else if (bx < 76) { int r = bx - 50; lvl = 1; p0 = (r % 13) * 128; d0 = (r / 13) * 128; }
    else              { int r = bx - 76; lvl = 2; p0 = (r & 3) * 128;  d0 = (r >> 2) * 128; }
    const int C     = 128 << lvl;
    const int HW    = 6400 >> (2 * lvl);
    const int HWpad = (lvl == 0) ? 6400 : (lvl == 1 ? 1664 : 512);
    const int NC    = C >> 5;

    extern __shared__ uint32_t dsm[];
    const int tid  = threadIdx.x;
    const int lane = tid & 31;
    const int wid  = tid >> 5;
    const int m_off = (wid & 1) * 64;
    const int n_off = (wid >> 1) * 32;
    const int g  = lane >> 2;
    const int tg = lane & 3;
    const uint32_t smb = smem_u32(dsm);

    const __nv_bfloat16* wA1 = P.wa[lvl] + (size_t)d0 * C;
    const __nv_bfloat16* wA2 = P.wb[lvl] + (size_t)d0 * C;
    const __nv_bfloat16* xB1 = P.xa[lvl] + (size_t)n * C * HWpad + p0;
    const __nv_bfloat16* xB2 = P.xb[lvl] + (size_t)n * C * HWpad + p0;

    float acc[4][4][4];
#pragma unroll
    for (int mi = 0; mi < 4; mi++)
#pragma unroll
        for (int ni = 0; ni < 4; ni++)
#pragma unroll
            for (int r = 0; r < 4; r++) acc[mi][ni][r] = 0.f;

    // precomputed staging slots (2 per tile kind per thread)
    const int ar0 = tid >> 2,          acb0 = tid & 3;
    const int ar1 = (tid + 256) >> 2,  acb1 = (tid + 256) & 3;
    const int br0 = tid >> 4,          bnb0 = tid & 15;
    const int br1 = (tid + 256) >> 4,  bnb1 = (tid + 256) & 15;
    const uint32_t adof0 = ar0 * 64 + ((acb0 ^ ((ar0 >> 1) & 3)) << 4);
    const uint32_t adof1 = ar1 * 64 + ((acb1 ^ ((ar1 >> 1) & 3)) << 4);
    const uint32_t bdof0 = br0 * 256 + ((bnb0 ^ (br0 & 7)) << 4);
    const uint32_t bdof1 = br1 * 256 + ((bnb1 ^ (br1 & 7)) << 4);

#define STAGE(BUF, KC)                                                              \
    do {                                                                            \
        int k0_ = (KC) * 32;                                                        \
        uint32_t bbuf = smb + (BUF) * 32768;                                        \
        cpa16(bbuf + adof0,         wA1 + (size_t)ar0 * C + k0_ + acb0 * 8);        \
        cpa16(bbuf + adof1,         wA1 + (size_t)ar1 * C + k0_ + acb1 * 8);        \
        cpa16(bbuf + 8192 + adof0,  wA2 + (size_t)ar0 * C + k0_ + acb0 * 8);        \
        cpa16(bbuf + 8192 + adof1,  wA2 + (size_t)ar1 * C + k0_ + acb1 * 8);        \
        cpa16(bbuf + 16384 + bdof0, xB1 + (size_t)(k0_ + br0) * HWpad + bnb0 * 8);  \
        cpa16(bbuf + 16384 + bdof1, xB1 + (size_t)(k0_ + br1) * HWpad + bnb1 * 8);  \
        cpa16(bbuf + 24576 + bdof0, xB2 + (size_t)(k0_ + br0) * HWpad + bnb0 * 8);  \
        cpa16(bbuf + 24576 + bdof1, xB2 + (size_t)(k0_ + br1) * HWpad + bnb1 * 8);  \
        asm volatile("cp.async.commit_group;");                                     \
    } while (0)

    STAGE(0, 0);

    for (int kc = 0; kc < NC; kc++) {
        int cur = kc & 1;
        if (kc + 1 < NC) {
            STAGE(cur ^ 1, kc + 1);
            asm volatile("cp.async.wait_group 1;");
        } else {
            asm volatile("cp.async.wait_group 0;");
        }
        __syncthreads();

        uint32_t base = smb + cur * 32768;
#pragma unroll
        for (int ks = 0; ks < 2; ks++) {
            // B fragments: 2 nip x (hi,lo), each x4.trans covers 2 n-atoms
            uint32_t bhf[2][4], blf[2][4];
            int brow = ks * 16 + (lane & 15);
            int nbb  = (n_off >> 3) + (lane >> 4);
#pragma unroll
            for (int nip = 0; nip < 2; nip++) {
                uint32_t boff = brow * 256 + (((nbb + nip * 2) ^ (brow & 7)) << 4);
                ldm_x4t(bhf[nip], base + 16384 + boff);
                ldm_x4t(blf[nip], base + 24576 + boff);
            }
#pragma unroll
            for (int mi = 0; mi < 4; mi++) {
                int arow = m_off + mi * 16 + (lane & 15);
                int cb   = ks * 2 + (lane >> 4);
                uint32_t aoff = arow * 64 + ((cb ^ ((arow >> 1) & 3)) << 4);
                uint32_t ah[4], al[4];
                ldm_x4(ah, base + aoff);
                ldm_x4(al, base + 8192 + aoff);
#pragma unroll
                for (int ni = 0; ni < 4; ni++) {
                    const uint32_t* bh = &bhf[ni >> 1][(ni & 1) * 2];
                    const uint32_t* bl = &blf[ni >> 1][(ni & 1) * 2];
                    mma16(acc[mi][ni], ah, bh);
                    mma16(acc[mi][ni], ah, bl);
                    mma16(acc[mi][ni], al, bh);
                }
            }
        }
        __syncthreads();
    }

    // epilogue: BN + SiLU (same output map as tf32 m16n8)
    const float* gg  = P.gg[lvl];
    const float* bbp = P.bb[lvl];
    const float* mm  = P.mm[lvl];
    const float* vv  = P.vv[lvl];
    float*       pf  = P.pf[lvl];
#pragma unroll
    for (int mi = 0; mi < 4; mi++) {
        int r0 = d0 + m_off + mi * 16 + g;
        int r1 = r0 + 8;
        float sc0 = gg[r0] * (1.0f / sqrtf(vv[r0] + 1e-5f));
        float bi0 = bbp[r0] - mm[r0] * sc0;
        float sc1 = gg[r1] * (1.0f / sqrtf(vv[r1] + 1e-5f));
        float bi1 = bbp[r1] - mm[r1] * sc1;
        float* op0 = pf + ((size_t)n * C + r0) * HW;
        float* op1 = pf + ((size_t)n * C + r1) * HW;
#pragma unroll
        for (int ni = 0; ni < 4; ni++) {
            int p = p0 + n_off + ni * 8 + 2 * tg;
            if (p < HW) {
                *(float2*)(op0 + p) = make_float2(silu(acc[mi][ni][0] * sc0 + bi0),
                                                  silu(acc[mi][ni][1] * sc0 + bi0));
                *(float2*)(op1 + p) = make_float2(silu(acc[mi][ni][2] * sc1 + bi1),
                                                  silu(acc[mi][ni][3] * sc1 + bi1));
            }
        }
    }
}

// ---------------- corr (unchanged from R5) ----------------------------------------
template<int C, int H, int W, int STEP, int NG, int NT, int WINL>
__global__ void __launch_bounds__(NT) corr2_kernel(
    const float* __restrict__ pf, const float* __restrict__ mlpw,
    float* __restrict__ out, int out_off)
{
    constexpr int PAD = RAD * STEP;
    constexpr int W2  = W + 2 * PAD;
    constexpr int H2  = H + 2 * PAD;
    constexpr int HW  = H * W;
    constexpr int NW  = NT / 32;

    extern __shared__ float sm[];
    float* f1p  = sm;
    float* wred = sm + H2 * W2;

    const int c    = blockIdx.x;
    const int b    = blockIdx.y;
    const int n1   = b * TPP + (TPP - 1);
    const int n2a  = g_idx[b * TFF + 0];
    const int n2b  = g_idx[b * TFF + 1];
    const int tid  = threadIdx.x;
    const int wid  = tid >> 5;
    const int lane = tid & 31;

    const float* f1g = pf + ((size_t)n1  * C + c) * HW;
    const float* f2a = pf + ((size_t)n2a * C + c) * HW;
    const float* f2b = pf + ((size_t)n2b * C + c) * HW;

    for (int q = tid; q < H2 * W2; q += NT) {
        int hh = q / W2 - PAD;
        int ww = q % W2 - PAD;
        float v = 0.f;
        if ((unsigned)hh < (unsigned)H && (unsigned)ww < (unsigned)W)
            v = f1g[hh * W + ww];
        f1p[q] = v;
    }

    float fra[NG][4], frb[NG][4];
    int   basek[NG];
#pragma unroll
    for (int gi = 0; gi < NG; gi++) {
        int p = (tid + NT * gi) * 4;
        if (p < HW) {
            float4 va = *(const float4*)(f2a + p);
            float4 vb = *(const float4*)(f2b + p);
            fra[gi][0] = va.x; fra[gi][1] = va.y; fra[gi][2] = va.z; fra[gi][3] = va.w;
            frb[gi][0] = vb.x; frb[gi][1] = vb.y; frb[gi][2] = vb.z; frb[gi][3] = vb.w;
            basek[gi] = (p / W + PAD) * W2 + (p % W) + PAD;
        } else {
#pragma unroll
            for (int v = 0; v < 4; v++) { fra[gi][v] = 0.f; frb[gi][v] = 0.f; }
            basek[gi] = PAD * W2 + PAD;
        }
    }
    __syncthreads();

    if (WINL == 0) {
        for (int oy = 0; oy < 9; oy++) {
            int ro[NG];
            int dyo = (oy - RAD) * STEP * W2;
#pragma unroll
            for (int gi = 0; gi < NG; gi++) ro[gi] = basek[gi] + dyo;
#pragma unroll
            for (int ox = 0; ox < 9; ox++) {
                const int dxo = (ox - RAD) * STEP;
                float a0 = 0.f, a1 = 0.f, b0 = 0.f, b1 = 0.f;
#pragma unroll
                for (int gi = 0; gi < NG; gi++) {
                    float4 fv = *(const float4*)&f1p[ro[gi] + dxo];
                    a0 = fmaf(fv.x, fra[gi][0], a0);
                    a1 = fmaf(fv.y, fra[gi][1], a1);
                    a0 = fmaf(fv.z, fra[gi][2], a0);
                    a1 = fmaf(fv.w, fra[gi][3], a1);
                    b0 = fmaf(fv.x, frb[gi][0], b0);
                    b1 = fmaf(fv.y, frb[gi][1], b1);
                    b0 = fmaf(fv.z, frb[gi][2], b0);
                    b1 = fmaf(fv.w, frb[gi][3], b1);
                }
                float va = a0 + a1, vb = b0 + b1;
#pragma unroll
                for (int o = 16; o; o >>= 1) {
                    va += __shfl_xor_sync(0xffffffffu, va, o);
                    vb += __shfl_xor_sync(0xffffffffu, vb, o);
                }
                if (lane == 0) {
                    wred[(0 * NW + wid) * NS + oy * 9 + ox] = va;
                    wred[(1 * NW + wid) * NS + oy * 9 + ox] = vb;
                }
            }
        }
    } else {
        for (int oy = 0; oy < 9; oy++) {
            int dyo = (oy - RAD) * STEP * W2;
            float aA[9], aB[9];
#pragma unroll
            for (int ox = 0; ox < 9; ox++) { aA[ox] = 0.f; aB[ox] = 0.f; }
#pragma unroll
            for (int gi = 0; gi < NG; gi++) {
                const float* wp = &f1p[basek[gi] + dyo - 4 * STEP];
                float win[WINL > 0 ? WINL : 1];
#pragma unroll
                for (int t = 0; t < WINL / 4; t++) {
                    float4 v = *(const float4*)(wp + 4 * t);
                    win[4 * t] = v.x; win[4 * t + 1] = v.y;
                    win[4 * t + 2] = v.z; win[4 * t + 3] = v.w;
                }
#pragma unroll
                for (int ox = 0; ox < 9; ox++) {
#pragma unroll
                    for (int j = 0; j < 4; j++) {
                        aA[ox] = fmaf(win[STEP * ox + j], fra[gi][j], aA[ox]);
                        aB[ox] = fmaf(win[STEP * ox + j], frb[gi][j], aB[ox]);
                    }
                }
            }
#pragma unroll
            for (int ox = 0; ox < 9; ox++) {
                float va = aA[ox], vb = aB[ox];
#pragma unroll
                for (int o = 16; o; o >>= 1) {
                    va += __shfl_xor_sync(0xffffffffu, va, o);
                    vb += __shfl_xor_sync(0xffffffffu, vb, o);
                }
                if (lane == 0) {
                    wred[(0 * NW + wid) * NS + oy * 9 + ox] = va;
                    wred[(1 * NW + wid) * NS + oy * 9 + ox] = vb;
                }
            }
        }
    }
    __syncthreads();

    if (tid < 64) {
        int q = tid >> 5, l = tid & 31;
        const float* wr = wred + q * NW * NS;
        float v0, v1 = -1e30f, v2 = -1e30f;
        {
            float s0 = 0.f, s1 = 0.f, s2 = 0.f;
#pragma unroll
            for (int w = 0; w < NW; w++) {
                s0 += wr[w * NS + l];
                if (l + 32 < NS) s1 += wr[w * NS + l + 32];
                if (l + 64 < NS) s2 += wr[w * NS + l + 64];
            }
            v0 = s0;
            if (l + 32 < NS) v1 = s1;
            if (l + 64 < NS) v2 = s2;
        }
        float mx = fmaxf(v0, fmaxf(v1, v2));
#pragma unroll
        for (int o = 16; o; o >>= 1)
            mx = fmaxf(mx, __shfl_xor_sync(0xffffffffu, mx, o));
        float e0 = expf(v0 - mx);
        float e1 = (l + 32 < NS) ? expf(v1 - mx) : 0.f;
        float e2 = (l + 64 < NS) ? expf(v2 - mx) : 0.f;
        float w0 = mlpw[l];
        float w1 = (l + 32 < NS) ? mlpw[l + 32] : 0.f;
        float w2 = (l + 64 < NS) ? mlpw[l + 64] : 0.f;
        float ssum = e0 + e1 + e2;
        float dot  = e0 * w0 + e1 * w1 + e2 * w2;
#pragma unroll
        for (int o = 16; o; o >>= 1) {
            ssum += __shfl_xor_sync(0xffffffffu, ssum, o);
            dot  += __shfl_xor_sync(0xffffffffu, dot,  o);
        }
        if (l == 0)
            out[out_off + (b * TFF + q) * C + c] = dot / ssum;
    }
}

// ---------------- launch ----------------------------------------------------------
extern "C" void kernel_launch(void* const* d_in, const int* in_sizes, int n_in,
                              void* d_out, int out_size)
{
    int map_sig [21] = {0,1,2, 3,4,5,6,7, 8,9,10,11,12, 13,14,15,16,17, 18,19,20};
    int map_dict[21] = {0,6,12, 1,2,3,4,5, 7,8,9,10,11, 13,14,15,16,17, 18,19,20};
    const int* map = (in_sizes[1] == 16384) ? map_dict : map_sig;

    const float* mlpw = (const float*)d_in[map[18]];
    const int*   pci  = (const int*)d_in[map[19]];
    const int*   fci  = (const int*)d_in[map[20]];
    float* out = (float*)d_out;

    void* pv;
    cudaGetSymbolAddress(&pv, g_pf0);  float* pf0 = (float*)pv;
    cudaGetSymbolAddress(&pv, g_pf1);  float* pf1 = (float*)pv;
    cudaGetSymbolAddress(&pv, g_pf2);  float* pf2 = (float*)pv;
    __nv_bfloat16 *w0a, *w0b, *w1a, *w1b, *w2a, *w2b;
    __nv_bfloat16 *x0a, *x0b, *x1a, *x1b, *x2a, *x2b;
    cudaGetSymbolAddress(&pv, g_w0a); w0a = (__nv_bfloat16*)pv;
    cudaGetSymbolAddress(&pv, g_w0b); w0b = (__nv_bfloat16*)pv;
    cudaGetSymbolAddress(&pv, g_w1a); w1a = (__nv_bfloat16*)pv;
    cudaGetSymbolAddress(&pv, g_w1b); w1b = (__nv_bfloat16*)pv;
    cudaGetSymbolAddress(&pv, g_w2a); w2a = (__nv_bfloat16*)pv;
    cudaGetSymbolAddress(&pv, g_w2b); w2b = (__nv_bfloat16*)pv;
    cudaGetSymbolAddress(&pv, g_x0a); x0a = (__nv_bfloat16*)pv;
    cudaGetSymbolAddress(&pv, g_x0b); x0b = (__nv_bfloat16*)pv;
    cudaGetSymbolAddress(&pv, g_x1a); x1a = (__nv_bfloat16*)pv;
    cudaGetSymbolAddress(&pv, g_x1b); x1b = (__nv_bfloat16*)pv;
    cudaGetSymbolAddress(&pv, g_x2a); x2a = (__nv_bfloat16*)pv;
    cudaGetSymbolAddress(&pv, g_x2b); x2b = (__nv_bfloat16*)pv;

    prep_kernel<<<1, 1>>>(pci, fci);
    wsplit_kernel<<<(128*128 + 255) / 256, 256>>>((const float*)d_in[map[3]],  w0a, w0b, 128*128);
    wsplit_kernel<<<(256*256 + 255) / 256, 256>>>((const float*)d_in[map[8]],  w1a, w1b, 256*256);
    wsplit_kernel<<<(512*512 + 255) / 256, 256>>>((const float*)d_in[map[13]], w2a, w2b, 512*512);

    xsplit_kernel<<<dim3((128*6400 + 255) / 256, 1, NFR), 256>>>(
        (const float*)d_in[map[0]], x0a, x0b, 128, 6400, 6400);
    xsplit_kernel<<<dim3((256*1664 + 255) / 256, 1, NFR), 256>>>(
        (const float*)d_in[map[1]], x1a, x1b, 256, 1600, 1664);
    xsplit_kernel<<<dim3((512*512 + 255) / 256, 1, NFR), 256>>>(
        (const float*)d_in[map[2]], x2a, x2b, 512, 400, 512);

    ConvTC P;
    P.wa[0] = w0a; P.wa[1] = w1a; P.wa[2] = w2a;
    P.wb[0] = w0b; P.wb[1] = w1b; P.wb[2] = w2b;
    P.xa[0] = x0a; P.xa[1] = x1a; P.xa[2] = x2a;
    P.xb[0] = x0b; P.xb[1] = x1b; P.xb[2] = x2b;
    P.gg[0] = (const float*)d_in[map[4]];  P.gg[1] = (const float*)d_in[map[9]];   P.gg[2] = (const float*)d_in[map[14]];
    P.bb[0] = (const float*)d_in[map[5]];  P.bb[1] = (const float*)d_in[map[10]];  P.bb[2] = (const float*)d_in[map[15]];
    P.mm[0] = (const float*)d_in[map[6]];  P.mm[1] = (const float*)d_in[map[11]];  P.mm[2] = (const float*)d_in[map[16]];
    P.vv[0] = (const float*)d_in[map[7]];  P.vv[1] = (const float*)d_in[map[12]];  P.vv[2] = (const float*)d_in[map[17]];
    P.pf[0] = pf0; P.pf[1] = pf1; P.pf[2] = pf2;

    cudaFuncSetAttribute(conv_bf16_kernel,
                         cudaFuncAttributeMaxDynamicSharedMemorySize, 65536);
    conv_bf16_kernel<<<dim3(92, 1, NFR), 256, 65536>>>(P);

    size_t sm0 = (size_t)(112 * 112 + 2 * 8 * NS) * sizeof(float);
    size_t sm1 = (size_t)( 56 *  56 + 2 * 8 * NS) * sizeof(float);
    size_t sm2 = (size_t)( 28 *  28 + 2 * 4 * NS) * sizeof(float);
    cudaFuncSetAttribute((const void*)corr2_kernel<128, 80, 80, 4, 7, 256, 0>,
                         cudaFuncAttributeMaxDynamicSharedMemorySize, 65536);

    corr2_kernel<128, 80, 80, 4, 7, 256,  0><<<dim3(128, BB), 256, sm0>>>(pf0, mlpw, out, 0);
    corr2_kernel<256, 40, 40, 2, 2, 256, 20><<<dim3(256, BB), 256, sm1>>>(pf1, mlpw, out, 1024);
    corr2_kernel<512, 20, 20, 1, 1, 128, 12><<<dim3(512, BB), 128, sm2>>>(pf2, mlpw, out, 3072);
}

// round 8
// speedup vs baseline: 2.1842x; 1.1630x over previous
#include <cuda_runtime.h>
#include <cuda_bf16.h>
#include <math.h>
#include <stdint.h>

#define BB    4
#define TPP   4
#define TFF   2
#define NPAIR (BB*TFF)
#define RAD   4
#define NS    81
#define NFR   (BB*TPP)

// ---------------- scratch ---------------------------------------------------------
__device__ int   g_idx[NPAIR];
__device__ int   g_needed[NFR];
__device__ float g_pf0[(size_t)NFR * 128 * 6400];
__device__ float g_pf1[(size_t)NFR * 256 * 1600];
__device__ float g_pf2[(size_t)NFR * 512 * 400];
__device__ __nv_bfloat16 g_w0a[128*128],  g_w0b[128*128];
__device__ __nv_bfloat16 g_w1a[256*256],  g_w1b[256*256];
__device__ __nv_bfloat16 g_w2a[512*512],  g_w2b[512*512];
__device__ __nv_bfloat16 g_x0a[(size_t)NFR*128*6400], g_x0b[(size_t)NFR*128*6400];
__device__ __nv_bfloat16 g_x1a[(size_t)NFR*256*1664], g_x1b[(size_t)NFR*256*1664];
__device__ __nv_bfloat16 g_x2a[(size_t)NFR*512*512],  g_x2b[(size_t)NFR*512*512];

// ---------------- prep ------------------------------------------------------------
__global__ void prep_kernel(const int* __restrict__ pci, const int* __restrict__ fci)
{
    if (threadIdx.x != 0 || blockIdx.x != 0) return;
    for (int n = 0; n < NFR; n++) g_needed[n] = 0;
    for (int i = 0; i < BB; i++) {
        int p_pos = TPP - 2;
        for (int j = 0; j < TFF; j++) {
            int f_i = fci[i * TFF + j];
            while (p_pos >= 0) {
                if (p_pos == 0 || f_i < -pci[i * TPP + p_pos - 1]) {
                    int id = p_pos + i * TPP;
                    g_idx[i * TFF + j] = id;
                    g_needed[id] = 1;
                    break;
                }
                p_pos--;
            }
        }
        g_needed[i * TPP + (TPP - 1)] = 1;
    }
}

// ---------------- vectorized split kernels (8 elems / thread) ---------------------
union BV8 { __nv_bfloat16 h[8]; uint4 u; };

__device__ __forceinline__ void split8(const float* v, uint4* ua, uint4* ub)
{
    BV8 a, b;
#pragma unroll
    for (int j = 0; j < 8; j++) {
        __nv_bfloat16 h = __float2bfloat16(v[j]);
        a.h[j] = h;
        b.h[j] = __float2bfloat16(v[j] - __bfloat162float(h));
    }
    *ua = a.u; *ub = b.u;
}

__global__ void wsplit_kernel(const float* __restrict__ w,
                              __nv_bfloat16* __restrict__ wa,
                              __nv_bfloat16* __restrict__ wb, int nElems)
{
    int i = (blockIdx.x * 256 + threadIdx.x) * 8;
    if (i < nElems) {
        float v[8];
        *(float4*)&v[0] = *(const float4*)(w + i);
        *(float4*)&v[4] = *(const float4*)(w + i + 4);
        split8(v, (uint4*)(wa + i), (uint4*)(wb + i));
    }
}

__global__ void xsplit_kernel(const float* __restrict__ x,
                              __nv_bfloat16* __restrict__ xa,
                              __nv_bfloat16* __restrict__ xb,
                              int C, int HW, int HWpad)
{
    int n = blockIdx.z;
    if (!g_needed[n]) return;
    int i = (blockIdx.x * 256 + threadIdx.x) * 8;
    int tot = C * HWpad;
    if (i >= tot) return;
    int c = i / HWpad, p = i - c * HWpad;
    float v[8];
    if (p + 8 <= HW) {
        const float* s = x + (size_t)n * C * HW + (size_t)c * HW + p;
        *(float4*)&v[0] = *(const float4*)s;
        *(float4*)&v[4] = *(const float4*)(s + 4);
    } else {
#pragma unroll
        for (int j = 0; j < 8; j++) v[j] = 0.f;
    }
    size_t o = (size_t)n * tot + i;
    split8(v, (uint4*)(xa + o), (uint4*)(xb + o));
}

// ---------------- mma.sync bf16 helpers -------------------------------------------
__device__ __forceinline__ uint32_t smem_u32(const void* p)
{
    uint32_t a;
    asm("{ .reg .u64 t; cvta.to.shared.u64 t, %1; cvt.u32.u64 %0, t; }" : "=r"(a) : "l"(p));
    return a;
}

__device__ __forceinline__ void ldm_x4(uint32_t* r, uint32_t addr)
{
    asm volatile("ldmatrix.sync.aligned.m8n8.x4.shared.b16 {%0,%1,%2,%3}, [%4];"
                 : "=r"(r[0]), "=r"(r[1]), "=r"(r[2]), "=r"(r[3]) : "r"(addr));
}

__device__ __forceinline__ void ldm_x4t(uint32_t* r, uint32_t addr)
{
    asm volatile("ldmatrix.sync.aligned.m8n8.x4.trans.shared.b16 {%0,%1,%2,%3}, [%4];"
                 : "=r"(r[0]), "=r"(r[1]), "=r"(r[2]), "=r"(r[3]) : "r"(addr));
}

__device__ __forceinline__ void mma16(float* c, const uint32_t* a, const uint32_t* b)
{
    asm volatile(
        "mma.sync.aligned.m16n8k16.row.col.f32.bf16.bf16.f32 "
        "{%0,%1,%2,%3}, {%4,%5,%6,%7}, {%8,%9}, {%0,%1,%2,%3};"
        : "+f"(c[0]), "+f"(c[1]), "+f"(c[2]), "+f"(c[3])
        : "r"(a[0]), "r"(a[1]), "r"(a[2]), "r"(a[3]), "r"(b[0]), "r"(b[1]));
}

__device__ __forceinline__ void cpa16(uint32_t dst, const void* src)
{
    asm volatile("cp.async.ca.shared.global [%0], [%1], 16;" :: "r"(dst), "l"(src));
}

__device__ __forceinline__ float silu(float y) { return y / (1.0f + expf(-y)); }

// ---------------- conv: bf16 3-term mma.sync, 3-stage pipeline --------------------
// Block tile 128(d) x 128(p), K-chunk 32 bf16. 8 warps = 2(m) x 4(n), warp 64x32.
// buffer (32 KB): Ah@0 [128][32]b16, Al@8192, Bh@16384 [32][128]b16, Bl@24576. 3 buffers.
struct ConvTC {
    const __nv_bfloat16 *wa[3], *wb[3], *xa[3], *xb[3];
    const float *gg[3], *bb[3], *mm[3], *vv[3];
    float *pf[3];
};

__global__ void __launch_bounds__(256, 2) conv_bf16_kernel(ConvTC P)
{
    int n = blockIdx.z;
    if (!g_needed[n]) return;

    int bx = blockIdx.x, lvl, p0, d0;
    if (bx < 50)      { lvl = 0; p0 = bx * 128; d0 = 0; }
    else if (bx < 76) { int r = bx - 50; lvl = 1; p0 = (r % 13) * 128; d0 = (r / 13) * 128; }
    else              { int r = bx - 76; lvl = 2; p0 = (r & 3) * 128;  d0 = (r >> 2) * 128; }
    const int C     = 128 << lvl;
    const int HW    = 6400 >> (2 * lvl);
    const int HWpad = (lvl == 0) ? 6400 : (lvl == 1 ? 1664 : 512);
    const int NC    = C >> 5;

    extern __shared__ uint32_t dsm[];
    const int tid  = threadIdx.x;
    const int lane = tid & 31;
    const int wid  = tid >> 5;
    const int m_off = (wid & 1) * 64;
    const int n_off = (wid >> 1) * 32;
    const int g  = lane >> 2;
    const int tg = lane & 3;
    const uint32_t smb = smem_u32(dsm);

    const __nv_bfloat16* wA1 = P.wa[lvl] + (size_t)d0 * C;
    const __nv_bfloat16* wA2 = P.wb[lvl] + (size_t)d0 * C;
    const __nv_bfloat16* xB1 = P.xa[lvl] + (size_t)n * C * HWpad + p0;
    const __nv_bfloat16* xB2 = P.xb[lvl] + (size_t)n * C * HWpad + p0;

    float acc[4][4][4];
#pragma unroll
    for (int mi = 0; mi < 4; mi++)
#pragma unroll
        for (int ni = 0; ni < 4; ni++)
#pragma unroll
            for (int r = 0; r < 4; r++) acc[mi][ni][r] = 0.f;

    const int ar0 = tid >> 2,          acb0 = tid & 3;
    const int ar1 = (tid + 256) >> 2,  acb1 = (tid + 256) & 3;
    const int br0 = tid >> 4,          bnb0 = tid & 15;
    const int br1 = (tid + 256) >> 4,  bnb1 = (tid + 256) & 15;
    const uint32_t adof0 = ar0 * 64 + ((acb0 ^ ((ar0 >> 1) & 3)) << 4);
    const uint32_t adof1 = ar1 * 64 + ((acb1 ^ ((ar1 >> 1) & 3)) << 4);
    const uint32_t bdof0 = br0 * 256 + ((bnb0 ^ (br0 & 7)) << 4);
    const uint32_t bdof1 = br1 * 256 + ((bnb1 ^ (br1 & 7)) << 4);

#define STAGE(BUF, KC)                                                              \
    do {                                                                            \
        int k0_ = (KC) * 32;                                                        \
        uint32_t bbuf = smb + (BUF) * 32768;                                        \
        cpa16(bbuf + adof0,         wA1 + (size_t)ar0 * C + k0_ + acb0 * 8);        \
        cpa16(bbuf + adof1,         wA1 + (size_t)ar1 * C + k0_ + acb1 * 8);        \
        cpa16(bbuf + 8192 + adof0,  wA2 + (size_t)ar0 * C + k0_ + acb0 * 8);        \
        cpa16(bbuf + 8192 + adof1,  wA2 + (size_t)ar1 * C + k0_ + acb1 * 8);        \
        cpa16(bbuf + 16384 + bdof0, xB1 + (size_t)(k0_ + br0) * HWpad + bnb0 * 8);  \
        cpa16(bbuf + 16384 + bdof1, xB1 + (size_t)(k0_ + br1) * HWpad + bnb1 * 8);  \
        cpa16(bbuf + 24576 + bdof0, xB2 + (size_t)(k0_ + br0) * HWpad + bnb0 * 8);  \
        cpa16(bbuf + 24576 + bdof1, xB2 + (size_t)(k0_ + br1) * HWpad + bnb1 * 8);  \
        asm volatile("cp.async.commit_group;");                                     \
    } while (0)

    // 3-stage prologue (NC >= 4 always)
    STAGE(0, 0);
    STAGE(1, 1);

    int cur = 0;
    for (int kc = 0; kc < NC; kc++) {
        if (kc + 1 < NC) {
            asm volatile("cp.async.wait_group 1;");
        } else {
            asm volatile("cp.async.wait_group 0;");
        }
        __syncthreads();   // buffer cur visible; prior reads of the stage target done

        if (kc + 2 < NC) {
            int nb = cur + 2;
            if (nb >= 3) nb -= 3;
            STAGE(nb, kc + 2);
        }

        uint32_t base = smb + cur * 32768;
#pragma unroll
        for (int ks = 0; ks < 2; ks++) {
            uint32_t bhf[2][4], blf[2][4];
            int brow = ks * 16 + (lane & 15);
            int nbb  = (n_off >> 3) + (lane >> 4);
#pragma unroll
            for (int nip = 0; nip < 2; nip++) {
                uint32_t boff = brow * 256 + (((nbb + nip * 2) ^ (brow & 7)) << 4);
                ldm_x4t(bhf[nip], base + 16384 + boff);
                ldm_x4t(blf[nip], base + 24576 + boff);
            }
#pragma unroll
            for (int mi = 0; mi < 4; mi++) {
                int arow = m_off + mi * 16 + (lane & 15);
                int cb   = ks * 2 + (lane >> 4);
                uint32_t aoff = arow * 64 + ((cb ^ ((arow >> 1) & 3)) << 4);
                uint32_t ah[4], al[4];
                ldm_x4(ah, base + aoff);
                ldm_x4(al, base + 8192 + aoff);
#pragma unroll
                for (int ni = 0; ni < 4; ni++) {
                    const uint32_t* bh = &bhf[ni >> 1][(ni & 1) * 2];
                    const uint32_t* bl = &blf[ni >> 1][(ni & 1) * 2];
                    mma16(acc[mi][ni], ah, bh);
                    mma16(acc[mi][ni], ah, bl);
                    mma16(acc[mi][ni], al, bh);
                }
            }
        }
        cur = (cur + 1 == 3) ? 0 : cur + 1;
    }

    const float* gg  = P.gg[lvl];
    const float* bbp = P.bb[lvl];
    const float* mm  = P.mm[lvl];
    const float* vv  = P.vv[lvl];
    float*       pf  = P.pf[lvl];
#pragma unroll
    for (int mi = 0; mi < 4; mi++) {
        int r0 = d0 + m_off + mi * 16 + g;
        int r1 = r0 + 8;
        float sc0 = gg[r0] * (1.0f / sqrtf(vv[r0] + 1e-5f));
        float bi0 = bbp[r0] - mm[r0] * sc0;
        float sc1 = gg[r1] * (1.0f / sqrtf(vv[r1] + 1e-5f));
        float bi1 = bbp[r1] - mm[r1] * sc1;
        float* op0 = pf + ((size_t)n * C + r0) * HW;
        float* op1 = pf + ((size_t)n * C + r1) * HW;
#pragma unroll
        for (int ni = 0; ni < 4; ni++) {
            int p = p0 + n_off + ni * 8 + 2 * tg;
            if (p < HW) {
                *(float2*)(op0 + p) = make_float2(silu(acc[mi][ni][0] * sc0 + bi0),
                                                  silu(acc[mi][ni][1] * sc0 + bi0));
                *(float2*)(op1 + p) = make_float2(silu(acc[mi][ni][2] * sc1 + bi1),
                                                  silu(acc[mi][ni][3] * sc1 + bi1));
            }
        }
    }
}

// ---------------- corr (unchanged from R5/R7) -------------------------------------
template<int C, int H, int W, int STEP, int NG, int NT, int WINL>
__global__ void __launch_bounds__(NT) corr2_kernel(
    const float* __restrict__ pf, const float* __restrict__ mlpw,
    float* __restrict__ out, int out_off)
{
    constexpr int PAD = RAD * STEP;
    constexpr int W2  = W + 2 * PAD;
    constexpr int H2  = H + 2 * PAD;
    constexpr int HW  = H * W;
    constexpr int NW  = NT / 32;

    extern __shared__ float sm[];
    float* f1p  = sm;
    float* wred = sm + H2 * W2;

    const int c    = blockIdx.x;
    const int b    = blockIdx.y;
    const int n1   = b * TPP + (TPP - 1);
    const int n2a  = g_idx[b * TFF + 0];
    const int n2b  = g_idx[b * TFF + 1];
    const int tid  = threadIdx.x;
    const int wid  = tid >> 5;
    const int lane = tid & 31;

    const float* f1g = pf + ((size_t)n1  * C + c) * HW;
    const float* f2a = pf + ((size_t)n2a * C + c) * HW;
    const float* f2b = pf + ((size_t)n2b * C + c) * HW;

    for (int q = tid; q < H2 * W2; q += NT) {
        int hh = q / W2 - PAD;
        int ww = q % W2 - PAD;
        float v = 0.f;
        if ((unsigned)hh < (unsigned)H && (unsigned)ww < (unsigned)W)
            v = f1g[hh * W + ww];
        f1p[q] = v;
    }

    float fra[NG][4], frb[NG][4];
    int   basek[NG];
#pragma unroll
    for (int gi = 0; gi < NG; gi++) {
        int p = (tid + NT * gi) * 4;
        if (p < HW) {
            float4 va = *(const float4*)(f2a + p);
            float4 vb = *(const float4*)(f2b + p);
            fra[gi][0] = va.x; fra[gi][1] = va.y; fra[gi][2] = va.z; fra[gi][3] = va.w;
            frb[gi][0] = vb.x; frb[gi][1] = vb.y; frb[gi][2] = vb.z; frb[gi][3] = vb.w;
            basek[gi] = (p / W + PAD) * W2 + (p % W) + PAD;
        } else {
#pragma unroll
            for (int v = 0; v < 4; v++) { fra[gi][v] = 0.f; frb[gi][v] = 0.f; }
            basek[gi] = PAD * W2 + PAD;
        }
    }
    __syncthreads();

    if (WINL == 0) {
        for (int oy = 0; oy < 9; oy++) {
            int ro[NG];
            int dyo = (oy - RAD) * STEP * W2;
#pragma unroll
            for (int gi = 0; gi < NG; gi++) ro[gi] = basek[gi] + dyo;
#pragma unroll
            for (int ox = 0; ox < 9; ox++) {
                const int dxo = (ox - RAD) * STEP;
                float a0 = 0.f, a1 = 0.f, b0 = 0.f, b1 = 0.f;
#pragma unroll
                for (int gi = 0; gi < NG; gi++) {
                    float4 fv = *(const float4*)&f1p[ro[gi] + dxo];
                    a0 = fmaf(fv.x, fra[gi][0], a0);
                    a1 = fmaf(fv.y, fra[gi][1], a1);
                    a0 = fmaf(fv.z, fra[gi][2], a0);
                    a1 = fmaf(fv.w, fra[gi][3], a1);
                    b0 = fmaf(fv.x, frb[gi][0], b0);
                    b1 = fmaf(fv.y, frb[gi][1], b1);
                    b0 = fmaf(fv.z, frb[gi][2], b0);
                    b1 = fmaf(fv.w, frb[gi][3], b1);
                }
                float va = a0 + a1, vb = b0 + b1;
#pragma unroll
                for (int o = 16; o; o >>= 1) {
                    va += __shfl_xor_sync(0xffffffffu, va, o);
                    vb += __shfl_xor_sync(0xffffffffu, vb, o);
                }
                if (lane == 0) {
                    wred[(0 * NW + wid) * NS + oy * 9 + ox] = va;
                    wred[(1 * NW + wid) * NS + oy * 9 + ox] = vb;
                }
            }
        }
    } else {
        for (int oy = 0; oy < 9; oy++) {
            int dyo = (oy - RAD) * STEP * W2;
            float aA[9], aB[9];
#pragma unroll
            for (int ox = 0; ox < 9; ox++) { aA[ox] = 0.f; aB[ox] = 0.f; }
#pragma unroll
            for (int gi = 0; gi < NG; gi++) {
                const float* wp = &f1p[basek[gi] + dyo - 4 * STEP];
                float win[WINL > 0 ? WINL : 1];
#pragma unroll
                for (int t = 0; t < WINL / 4; t++) {
                    float4 v = *(const float4*)(wp + 4 * t);
                    win[4 * t] = v.x; win[4 * t + 1] = v.y;
                    win[4 * t + 2] = v.z; win[4 * t + 3] = v.w;
                }
#pragma unroll
                for (int ox = 0; ox < 9; ox++) {
#pragma unroll
                    for (int j = 0; j < 4; j++) {
                        aA[ox] = fmaf(win[STEP * ox + j], fra[gi][j], aA[ox]);
                        aB[ox] = fmaf(win[STEP * ox + j], frb[gi][j], aB[ox]);
                    }
                }
            }
#pragma unroll
            for (int ox = 0; ox < 9; ox++) {
                float va = aA[ox], vb = aB[ox];
#pragma unroll
                for (int o = 16; o; o >>= 1) {
                    va += __shfl_xor_sync(0xffffffffu, va, o);
                    vb += __shfl_xor_sync(0xffffffffu, vb, o);
                }
                if (lane == 0) {
                    wred[(0 * NW + wid) * NS + oy * 9 + ox] = va;
                    wred[(1 * NW + wid) * NS + oy * 9 + ox] = vb;
                }
            }
        }
    }
    __syncthreads();

    if (tid < 64) {
        int q = tid >> 5, l = tid & 31;
        const float* wr = wred + q * NW * NS;
        float v0, v1 = -1e30f, v2 = -1e30f;
        {
            float s0 = 0.f, s1 = 0.f, s2 = 0.f;
#pragma unroll
            for (int w = 0; w < NW; w++) {
                s0 += wr[w * NS + l];
                if (l + 32 < NS) s1 += wr[w * NS + l + 32];
                if (l + 64 < NS) s2 += wr[w * NS + l + 64];
            }
            v0 = s0;
            if (l + 32 < NS) v1 = s1;
            if (l + 64 < NS) v2 = s2;
        }
        float mx = fmaxf(v0, fmaxf(v1, v2));
#pragma unroll
        for (int o = 16; o; o >>= 1)
            mx = fmaxf(mx, __shfl_xor_sync(0xffffffffu, mx, o));
        float e0 = expf(v0 - mx);
        float e1 = (l + 32 < NS) ? expf(v1 - mx) : 0.f;
        float e2 = (l + 64 < NS) ? expf(v2 - mx) : 0.f;
        float w0 = mlpw[l];
        float w1 = (l + 32 < NS) ? mlpw[l + 32] : 0.f;
        float w2 = (l + 64 < NS) ? mlpw[l + 64] : 0.f;
        float ssum = e0 + e1 + e2;
        float dot  = e0 * w0 + e1 * w1 + e2 * w2;
#pragma unroll
        for (int o = 16; o; o >>= 1) {
            ssum += __shfl_xor_sync(0xffffffffu, ssum, o);
            dot  += __shfl_xor_sync(0xffffffffu, dot,  o);
        }
        if (l == 0)
            out[out_off + (b * TFF + q) * C + c] = dot / ssum;
    }
}

// ---------------- launch ----------------------------------------------------------
extern "C" void kernel_launch(void* const* d_in, const int* in_sizes, int n_in,
                              void* d_out, int out_size)
{
    int map_sig [21] = {0,1,2, 3,4,5,6,7, 8,9,10,11,12, 13,14,15,16,17, 18,19,20};
    int map_dict[21] = {0,6,12, 1,2,3,4,5, 7,8,9,10,11, 13,14,15,16,17, 18,19,20};
    const int* map = (in_sizes[1] == 16384) ? map_dict : map_sig;

    const float* mlpw = (const float*)d_in[map[18]];
    const int*   pci  = (const int*)d_in[map[19]];
    const int*   fci  = (const int*)d_in[map[20]];
    float* out = (float*)d_out;

    void* pv;
    cudaGetSymbolAddress(&pv, g_pf0);  float* pf0 = (float*)pv;
    cudaGetSymbolAddress(&pv, g_pf1);  float* pf1 = (float*)pv;
    cudaGetSymbolAddress(&pv, g_pf2);  float* pf2 = (float*)pv;
    __nv_bfloat16 *w0a, *w0b, *w1a, *w1b, *w2a, *w2b;
    __nv_bfloat16 *x0a, *x0b, *x1a, *x1b, *x2a, *x2b;
    cudaGetSymbolAddress(&pv, g_w0a); w0a = (__nv_bfloat16*)pv;
    cudaGetSymbolAddress(&pv, g_w0b); w0b = (__nv_bfloat16*)pv;
    cudaGetSymbolAddress(&pv, g_w1a); w1a = (__nv_bfloat16*)pv;
    cudaGetSymbolAddress(&pv, g_w1b); w1b = (__nv_bfloat16*)pv;
    cudaGetSymbolAddress(&pv, g_w2a); w2a = (__nv_bfloat16*)pv;
    cudaGetSymbolAddress(&pv, g_w2b); w2b = (__nv_bfloat16*)pv;
    cudaGetSymbolAddress(&pv, g_x0a); x0a = (__nv_bfloat16*)pv;
    cudaGetSymbolAddress(&pv, g_x0b); x0b = (__nv_bfloat16*)pv;
    cudaGetSymbolAddress(&pv, g_x1a); x1a = (__nv_bfloat16*)pv;
    cudaGetSymbolAddress(&pv, g_x1b); x1b = (__nv_bfloat16*)pv;
    cudaGetSymbolAddress(&pv, g_x2a); x2a = (__nv_bfloat16*)pv;
    cudaGetSymbolAddress(&pv, g_x2b); x2b = (__nv_bfloat16*)pv;

    prep_kernel<<<1, 1>>>(pci, fci);
    wsplit_kernel<<<(128*128/8 + 255) / 256, 256>>>((const float*)d_in[map[3]],  w0a, w0b, 128*128);
    wsplit_kernel<<<(256*256/8 + 255) / 256, 256>>>((const float*)d_in[map[8]],  w1a, w1b, 256*256);
    wsplit_kernel<<<(512*512/8 + 255) / 256, 256>>>((const float*)d_in[map[13]], w2a, w2b, 512*512);

    xsplit_kernel<<<dim3((128*6400/8 + 255) / 256, 1, NFR), 256>>>(
        (const float*)d_in[map[0]], x0a, x0b, 128, 6400, 6400);
    xsplit_kernel<<<dim3((256*1664/8 + 255) / 256, 1, NFR), 256>>>(
        (const float*)d_in[map[1]], x1a, x1b, 256, 1600, 1664);
    xsplit_kernel<<<dim3((512*512/8 + 255) / 256, 1, NFR), 256>>>(
        (const float*)d_in[map[2]], x2a, x2b, 512, 400, 512);

    ConvTC P;
    P.wa[0] = w0a; P.wa[1] = w1a; P.wa[2] = w2a;
    P.wb[0] = w0b; P.wb[1] = w1b; P.wb[2] = w2b;
    P.xa[0] = x0a; P.xa[1] = x1a; P.xa[2] = x2a;
    P.xb[0] = x0b; P.xb[1] = x1b; P.xb[2] = x2b;
    P.gg[0] = (const float*)d_in[map[4]];  P.gg[1] = (const float*)d_in[map[9]];   P.gg[2] = (const float*)d_in[map[14]];
    P.bb[0] = (const float*)d_in[map[5]];  P.bb[1] = (const float*)d_in[map[10]];  P.bb[2] = (const float*)d_in[map[15]];
    P.mm[0] = (const float*)d_in[map[6]];  P.mm[1] = (const float*)d_in[map[11]];  P.mm[2] = (const float*)d_in[map[16]];
    P.vv[0] = (const float*)d_in[map[7]];  P.vv[1] = (const float*)d_in[map[12]];  P.vv[2] = (const float*)d_in[map[17]];
    P.pf[0] = pf0; P.pf[1] = pf1; P.pf[2] = pf2;

    cudaFuncSetAttribute(conv_bf16_kernel,
                         cudaFuncAttributeMaxDynamicSharedMemorySize, 3 * 32768);
    conv_bf16_kernel<<<dim3(92, 1, NFR), 256, 3 * 32768>>>(P);

    size_t sm0 = (size_t)(112 * 112 + 2 * 8 * NS) * sizeof(float);
    size_t sm1 = (size_t)( 56 *  56 + 2 * 8 * NS) * sizeof(float);
    size_t sm2 = (size_t)( 28 *  28 + 2 * 4 * NS) * sizeof(float);
    cudaFuncSetAttribute((const void*)corr2_kernel<128, 80, 80, 4, 7, 256, 0>,
                         cudaFuncAttributeMaxDynamicSharedMemorySize, 65536);

    corr2_kernel<128, 80, 80, 4, 7, 256,  0><<<dim3(128, BB), 256, sm0>>>(pf0, mlpw, out, 0);
    corr2_kernel<256, 40, 40, 2, 2, 256, 20><<<dim3(256, BB), 256, sm1>>>(pf1, mlpw, out, 1024);
    corr2_kernel<512, 20, 20, 1, 1, 128, 12><<<dim3(512, BB), 128, sm2>>>(pf2, mlpw, out, 3072);
}